// round 13
// baseline (speedup 1.0000x reference)
#include <cuda_runtime.h>
#include <cuda_fp16.h>
#include <cstdint>

#define B_SZ   16384
#define D_SZ   256
#define H_SZ   8192
#define K_TOP  32
#define CAND_K   36     // min candidates needed at a grid threshold
#define CAND_MAX 256    // hit cap / candidate buffer size
#define TK_MARGIN 4     // ulp margin below chosen threshold
#define ROWG   4096
#define NGRP   (B_SZ / ROWG)
#define HIT_T0 2.1f     // encoder-side hit filter (9-sigma below s32 stat)

// select staging
#define RS_BATCH 16
#define RS_PITCH 260
#define SEL_SMEM_FLOATS (256 + CAND_MAX + CAND_MAX + RS_BATCH * RS_PITCH)
#define SEL_SMEM_BYTES  (SEL_SMEM_FLOATS * 4)

// ---------------------------------------------------------------------------
// Scratch
// ---------------------------------------------------------------------------
__device__ __half g_xh [B_SZ * D_SZ];                 // fp16(x - b_dec)
__device__ __half g_weh[H_SZ * D_SZ];                 // fp16(W_enc)
__device__ uint32_t g_hits[(size_t)B_SZ * CAND_MAX];  // (fp16val<<16)|idx
__device__ int   g_hcnt[B_SZ];
__device__ int   g_counts[H_SZ];
__device__ float g_colsum[64 * D_SZ];
__device__ float g_qpart[64];
__device__ float g_e2part[B_SZ];

// ---------------------------------------------------------------------------
// Helpers
// ---------------------------------------------------------------------------
__device__ __forceinline__ uint32_t smem_u32(const void* p) {
    uint32_t a;
    asm("{ .reg .u64 t; cvta.to.shared.u64 t, %1; cvt.u32.u64 %0, t; }" : "=r"(a) : "l"(p));
    return a;
}
#define CP_ASYNC16(dst, src) \
    asm volatile("cp.async.cg.shared.global [%0], [%1], 16;" :: "r"(dst), "l"(src))
#define CP_COMMIT() asm volatile("cp.async.commit_group;")
#define CP_WAIT(n)  asm volatile("cp.async.wait_group %0;" :: "n"(n))

__device__ __forceinline__ void ldsm_x4(uint32_t& r0, uint32_t& r1, uint32_t& r2, uint32_t& r3,
                                        uint32_t addr) {
    asm volatile("ldmatrix.sync.aligned.m8n8.x4.shared.b16 {%0,%1,%2,%3}, [%4];"
                 : "=r"(r0), "=r"(r1), "=r"(r2), "=r"(r3) : "r"(addr));
}
__device__ __forceinline__ void mma_16816(float* c, uint32_t a0, uint32_t a1, uint32_t a2,
                                          uint32_t a3, uint32_t b0, uint32_t b1) {
    asm volatile(
        "mma.sync.aligned.m16n8k16.row.col.f32.f16.f16.f32 "
        "{%0,%1,%2,%3}, {%4,%5,%6,%7}, {%8,%9}, {%0,%1,%2,%3};"
        : "+f"(c[0]), "+f"(c[1]), "+f"(c[2]), "+f"(c[3])
        : "r"(a0), "r"(a1), "r"(a2), "r"(a3), "r"(b0), "r"(b1));
}
__device__ __forceinline__ void emit_hit(int row, int hcol, float v) {
    int p = atomicAdd(&g_hcnt[row], 1);
    if (p < CAND_MAX) {
        uint32_t pk = ((uint32_t)__half_as_ushort(__float2half_rn(v)) << 16) | (uint32_t)hcol;
        g_hits[(size_t)row * CAND_MAX + p] = pk;
    }
}

// ---------------------------------------------------------------------------
// Kernel 0: convert x -> fp16(x - b_dec), W_enc -> fp16
// ---------------------------------------------------------------------------
__global__ __launch_bounds__(256) void conv_kernel(
    const float* __restrict__ x, const float* __restrict__ W_enc,
    const float* __restrict__ b_dec)
{
    int b = blockIdx.x, t = threadIdx.x;
    if (b < 2048) {
        size_t e0 = ((size_t)b * 256 + t) * 8;
        int col = (int)(e0 & (D_SZ - 1));
        float4 v0 = *(const float4*)(x + e0);
        float4 v1 = *(const float4*)(x + e0 + 4);
        float4 d0 = *(const float4*)(b_dec + col);
        float4 d1 = *(const float4*)(b_dec + col + 4);
        __half o[8];
        o[0]=__float2half_rn(v0.x-d0.x); o[1]=__float2half_rn(v0.y-d0.y);
        o[2]=__float2half_rn(v0.z-d0.z); o[3]=__float2half_rn(v0.w-d0.w);
        o[4]=__float2half_rn(v1.x-d1.x); o[5]=__float2half_rn(v1.y-d1.y);
        o[6]=__float2half_rn(v1.z-d1.z); o[7]=__float2half_rn(v1.w-d1.w);
        *(uint4*)(g_xh + e0) = *(uint4*)o;
    } else {
        size_t e0 = ((size_t)(b - 2048) * 256 + t) * 8;
        float4 v0 = *(const float4*)(W_enc + e0);
        float4 v1 = *(const float4*)(W_enc + e0 + 4);
        __half o[8];
        o[0]=__float2half_rn(v0.x); o[1]=__float2half_rn(v0.y);
        o[2]=__float2half_rn(v0.z); o[3]=__float2half_rn(v0.w);
        o[4]=__float2half_rn(v1.x); o[5]=__float2half_rn(v1.y);
        o[6]=__float2half_rn(v1.z); o[7]=__float2half_rn(v1.w);
        *(uint4*)(g_weh + e0) = *(uint4*)o;
    }
}

// ---------------------------------------------------------------------------
// Kernel 1: column stats of x + zero counts + zero hit counters
// ---------------------------------------------------------------------------
__global__ __launch_bounds__(256) void colstat_kernel(const float* __restrict__ x)
{
    __shared__ float red[256];
    int g = blockIdx.x, t = threadIdx.x;
    int gid = g * 256 + t;
    if (gid < H_SZ) g_counts[gid] = 0;
    g_hcnt[gid] = 0;                    // 64*256 == B_SZ exactly
    const float* xb = x + (size_t)(g * 256) * D_SZ;
    float s = 0.f, q = 0.f;
    #pragma unroll 8
    for (int r = 0; r < 256; r++) {
        float v = xb[r * D_SZ + t];
        s += v; q += v * v;
    }
    g_colsum[g * D_SZ + t] = s;
    red[t] = q; __syncthreads();
    for (int sft = 128; sft > 0; sft >>= 1) { if (t < sft) red[t] += red[t + sft]; __syncthreads(); }
    if (t == 0) g_qpart[g] = red[0];
}

// ---------------------------------------------------------------------------
// Kernel 2: encoder GEMM via mma.sync; epilogue emits hits (no acts store).
// MMA core identical to R12 (bit-identical accumulators).
// ---------------------------------------------------------------------------
#define KC2      64
#define PITCH2   72
#define STG2     (128 * PITCH2 * 2)
#define OFF2_A(p) ((p) * STG2)
#define OFF2_B(p) (2 * STG2 + (p) * STG2)
#define OFF2_BES (4 * STG2)
#define ESM2_TOTAL (OFF2_BES + 512)

__global__ __launch_bounds__(256, 2) void encode_kernel(const float* __restrict__ b_enc,
                                                        int rgBase)
{
    extern __shared__ char smem[];
    const uint32_t sbase = smem_u32(smem);
    const int t = threadIdx.x;
    const int wid = t >> 5, lane = t & 31;
    const int h0 = blockIdx.x * 128;
    const int r0 = rgBase + blockIdx.y * 128;

    const int wm = wid >> 2, wn = wid & 3;
    const int m0w = wm * 64, n0w = wn * 32;

    const char* gA = (const char*)(g_xh  + (size_t)r0 * D_SZ);
    const char* gB = (const char*)(g_weh + (size_t)h0 * D_SZ);

    auto load_stage = [&](int s, int p) {
        #pragma unroll
        for (int i = 0; i < 4; i++) {
            int idx = t + 256 * i;
            int row = idx >> 3, q = idx & 7;
            uint32_t dOff = (uint32_t)((row * PITCH2 + q * 8) * 2);
            size_t gOff = ((size_t)row * D_SZ + s * KC2 + q * 8) * 2;
            CP_ASYNC16(sbase + OFF2_A(p) + dOff, gA + gOff);
            CP_ASYNC16(sbase + OFF2_B(p) + dOff, gB + gOff);
        }
        CP_COMMIT();
    };

    load_stage(0, 0);
    load_stage(1, 1);
    ((float*)(smem + OFF2_BES))[t & 127] = b_enc[h0 + (t & 127)];

    float acc[16][4];
    #pragma unroll
    for (int f = 0; f < 16; f++)
        #pragma unroll
        for (int e = 0; e < 4; e++) acc[f][e] = 0.f;

    const int aRow = lane & 15;
    const int aCol = (lane >> 4) << 3;
    const int bRow = ((lane >> 4) << 3) + (lane & 7);
    const int bCol = ((lane >> 3) & 1) << 3;

    CP_WAIT(1);
    __syncthreads();

    #pragma unroll
    for (int s = 0; s < 4; s++) {
        const int p = s & 1;
        const uint32_t aBase = sbase + OFF2_A(p) + ((m0w + aRow) * PITCH2 + aCol) * 2;
        const uint32_t bBase = sbase + OFF2_B(p) + ((n0w + bRow) * PITCH2 + bCol) * 2;
        #pragma unroll
        for (int k0 = 0; k0 < KC2; k0 += 16) {
            uint32_t a[4][4], b[2][4];
            #pragma unroll
            for (int i = 0; i < 4; i++)
                ldsm_x4(a[i][0], a[i][1], a[i][2], a[i][3],
                        aBase + (i * 16 * PITCH2 + k0) * 2);
            #pragma unroll
            for (int jp = 0; jp < 2; jp++)
                ldsm_x4(b[jp][0], b[jp][1], b[jp][2], b[jp][3],
                        bBase + (jp * 16 * PITCH2 + k0) * 2);
            #pragma unroll
            for (int i = 0; i < 4; i++)
                #pragma unroll
                for (int j = 0; j < 4; j++)
                    mma_16816(acc[i * 4 + j], a[i][0], a[i][1], a[i][2], a[i][3],
                              b[j >> 1][(j & 1) * 2], b[j >> 1][(j & 1) * 2 + 1]);
        }
        if (s < 2) {
            __syncthreads();
            load_stage(s + 2, p);
            CP_WAIT(1);
            __syncthreads();
        } else if (s == 2) {
            CP_WAIT(0);
            __syncthreads();
        }
    }

    // epilogue: bias + hit detection (ŝ >= HIT_T0) straight from registers
    const float* bes = (const float*)(smem + OFF2_BES);
    const int qr = lane >> 2, qc = lane & 3;
    #pragma unroll
    for (int i = 0; i < 4; i++) {
        #pragma unroll
        for (int j = 0; j < 4; j++) {
            int col = n0w + j * 8 + qc * 2;
            float b0 = bes[col], b1 = bes[col + 1];
            const float* c = acc[i * 4 + j];
            int mA = m0w + i * 16 + qr;
            float v0 = c[0] + b0, v1 = c[1] + b1;
            float v2 = c[2] + b0, v3 = c[3] + b1;
            int rA = r0 + mA, rB = r0 + mA + 8;
            if (v0 >= HIT_T0) emit_hit(rA, h0 + col,     v0);
            if (v1 >= HIT_T0) emit_hit(rA, h0 + col + 1, v1);
            if (v2 >= HIT_T0) emit_hit(rB, h0 + col,     v2);
            if (v3 >= HIT_T0) emit_hit(rB, h0 + col + 1, v3);
        }
    }
}

// ---------------------------------------------------------------------------
// Kernel 3: select+decode from hit lists. Probe grid on <=256 hit values,
// collect >= T-4ulp, exact staged rescore (verbatim sequential fmaf), rank,
// decode + counts + e^2. Uniform-branch fallback recomputes exactly (rare).
// ---------------------------------------------------------------------------
__global__ __launch_bounds__(256, 8) void select_kernel(
    const float* __restrict__ x, const float* __restrict__ W_enc,
    const float* __restrict__ b_enc, const float* __restrict__ b_dec,
    const float* __restrict__ W_dec, float* __restrict__ out,
    int rgBase)
{
    extern __shared__ float sm[];
    float* xs  = sm;                       // [256]
    float* cv  = sm + 256;                 // [CAND_MAX]
    int*   ci  = (int*)(sm + 256 + CAND_MAX);
    float* stg = sm + 256 + 2 * CAND_MAX;  // [RS_BATCH][RS_PITCH]; reused as red buf
    __shared__ int s_cnt;
    __shared__ float rv[K_TOP];
    __shared__ int   ri[K_TOP];

    const int row = rgBase + blockIdx.x;
    const int t = threadIdx.x;

    const float xv  = x[(size_t)row * D_SZ + t];
    const float bdv = b_dec[t];
    xs[t] = xv - bdv;
    if (t == 0) s_cnt = 0;

    const int cntraw = g_hcnt[row];
    const int cntc   = (cntraw < CAND_MAX) ? cntraw : CAND_MAX;
    uint32_t myval = 0, myidx = 0;
    if (t < cntc) {
        uint32_t pk = g_hits[(size_t)row * CAND_MAX + t];
        myval = pk >> 16;
        myidx = pk & 0xFFFFu;
    }
    __syncthreads();

    const bool fb = (cntc < CAND_K) || (cntraw >= CAND_MAX);   // uniform per block

    if (!fb) {
        // probe grid 2.1..2.8 on hit values; all hits >= 2.1 so grid[0] works
        const uint32_t TG[8] = {0x4033,0x4066,0x4099,0x40CD,0x4100,0x4133,0x4166,0x419A};
        int cg[8];
        #pragma unroll
        for (int j = 0; j < 8; j++)
            cg[j] = __syncthreads_count(t < cntc && myval >= TG[j]);
        int T = (int)TG[0];
        #pragma unroll
        for (int j = 7; j >= 1; j--) {      // take highest with count >= CAND_K
            if (cg[j] >= CAND_K) { T = (int)TG[j]; break; }
        }
        const uint32_t Tc = (uint32_t)(T - TK_MARGIN);
        if (t < cntc && myval >= Tc) {
            int p = atomicAdd(&s_cnt, 1);
            ci[p] = (int)myidx;
        }
        __syncthreads();
    } else {
        // exact fallback: recompute all H scores, adaptive threshold
        float thr = HIT_T0;
        for (int iter = 0; iter < 12; iter++) {
            if (t == 0) s_cnt = 0;
            __syncthreads();
            #pragma unroll 1
            for (int i = 0; i < H_SZ / 256; i++) {
                int idx = t + 256 * i;
                const float* wr = W_enc + (size_t)idx * D_SZ;
                float s = 0.f;
                #pragma unroll 8
                for (int k = 0; k < D_SZ; k++) s = fmaf(xs[k], __ldg(&wr[k]), s);
                s = fmaxf(s + b_enc[idx], 0.f);
                if (s >= thr) {
                    int p = atomicAdd(&s_cnt, 1);
                    if (p < CAND_MAX) ci[p] = idx;
                }
            }
            __syncthreads();
            int c = s_cnt;
            if (c >= CAND_K && c < CAND_MAX) break;
            thr = (c >= CAND_MAX) ? thr + 0.3f : thr - 0.4f;
            __syncthreads();
        }
    }
    const int cnt = (s_cnt < CAND_MAX) ? s_cnt : CAND_MAX;

    // rescore: staged coalesced, verbatim sequential fmaf chain
    for (int b0 = 0; b0 < cnt; b0 += RS_BATCH) {
        int nb = min(RS_BATCH, cnt - b0);
        for (int j = t; j < nb * 64; j += 256) {
            int r = j >> 6, c4 = j & 63;
            int idx = ci[b0 + r];
            float4 v = __ldg((const float4*)(W_enc + (size_t)idx * D_SZ) + c4);
            *(float4*)(stg + r * RS_PITCH + c4 * 4) = v;
        }
        __syncthreads();
        if (t < nb) {
            int idx = ci[b0 + t];
            const float* wrow = stg + t * RS_PITCH;
            float s = 0.f;
            #pragma unroll 8
            for (int k = 0; k < D_SZ; k++) s = fmaf(xs[k], wrow[k], s);
            cv[b0 + t] = fmaxf(s + b_enc[idx], 0.f);
        }
        __syncthreads();
    }

    // rank -> top-32 (value desc, index asc) + counts
    if (t < K_TOP) { rv[t] = 0.f; ri[t] = 0; }
    __syncthreads();
    if (t < cnt) {
        float v = cv[t]; int id = ci[t];
        int rank = 0;
        for (int j = 0; j < cnt; j++) {
            float vo = cv[j];
            rank += (vo > v) || (vo == v && ci[j] < id);
        }
        if (rank < K_TOP) {
            rv[rank] = v;
            ri[rank] = id;
            atomicAdd(&g_counts[id], 1);
        }
    }
    __syncthreads();

    // decode column t (identical arithmetic/order to prior decode)
    float acc = bdv;
    #pragma unroll
    for (int j = 0; j < K_TOP; j++)
        acc += rv[j] * __ldg(&W_dec[(size_t)ri[j] * D_SZ + t]);
    out[(size_t)row * D_SZ + t] = acc;

    float e = acc - xv;
    stg[t] = e * e;
    __syncthreads();
    for (int s = 128; s > 0; s >>= 1) {
        if (t < s) stg[t] += stg[t + s];
        __syncthreads();
    }
    if (t == 0) g_e2part[row] = stg[0];
}

// ---------------------------------------------------------------------------
// Kernel 4: finalize
// ---------------------------------------------------------------------------
__global__ __launch_bounds__(256) void finalize_kernel(float* __restrict__ out)
{
    __shared__ float red[256];
    __shared__ float sh_var, sh_q, sh_e2;
    int t = threadIdx.x;
    float S = 0.f;
    for (int g = 0; g < 64; g++) S += g_colsum[g * D_SZ + t];
    red[t] = S * S * (1.0f / (float)B_SZ);
    __syncthreads();
    for (int s = 128; s > 0; s >>= 1) { if (t < s) red[t] += red[t + s]; __syncthreads(); }
    if (t == 0) sh_var = red[0];
    __syncthreads();
    red[t] = (t < 64) ? g_qpart[t] : 0.f;
    __syncthreads();
    for (int s = 128; s > 0; s >>= 1) { if (t < s) red[t] += red[t + s]; __syncthreads(); }
    if (t == 0) sh_q = red[0];
    __syncthreads();
    float e2 = 0.f;
    for (int i = t; i < B_SZ; i += 256) e2 += g_e2part[i];
    red[t] = e2; __syncthreads();
    for (int s = 128; s > 0; s >>= 1) { if (t < s) red[t] += red[t + s]; __syncthreads(); }
    if (t == 0) sh_e2 = red[0];
    __syncthreads();
    if (t == 0) {
        float total_var = sh_q - sh_var;
        out[(size_t)B_SZ * D_SZ + H_SZ] = sh_e2 / total_var;
    }
    for (int i = t; i < H_SZ; i += 256)
        out[(size_t)B_SZ * D_SZ + i] = (float)g_counts[i];
}

// ---------------------------------------------------------------------------
// Launch: encode on second stream, overlapped with select of prior group.
// ---------------------------------------------------------------------------
static cudaStream_t g_s2 = nullptr;
static cudaEvent_t  g_evC = nullptr;
static cudaEvent_t  g_evE[NGRP];

extern "C" void kernel_launch(void* const* d_in, const int* in_sizes, int n_in,
                              void* d_out, int out_size)
{
    const float* x     = (const float*)d_in[0];
    const float* W_enc = (const float*)d_in[1];
    const float* b_enc = (const float*)d_in[2];
    const float* W_dec = (const float*)d_in[3];
    const float* b_dec = (const float*)d_in[4];
    float* out = (float*)d_out;

    if (g_s2 == nullptr) {
        cudaStreamCreateWithFlags(&g_s2, cudaStreamNonBlocking);
        cudaEventCreateWithFlags(&g_evC, cudaEventDisableTiming);
        for (int g = 0; g < NGRP; g++)
            cudaEventCreateWithFlags(&g_evE[g], cudaEventDisableTiming);
        cudaFuncSetAttribute(encode_kernel,
                             cudaFuncAttributeMaxDynamicSharedMemorySize, ESM2_TOTAL);
        cudaFuncSetAttribute(select_kernel,
                             cudaFuncAttributeMaxDynamicSharedMemorySize, SEL_SMEM_BYTES);
    }

    conv_kernel<<<3072, 256>>>(x, W_enc, b_dec);
    colstat_kernel<<<64, 256>>>(x);
    cudaEventRecord(g_evC, 0);
    cudaStreamWaitEvent(g_s2, g_evC, 0);

    encode_kernel<<<dim3(H_SZ / 128, ROWG / 128), 256, ESM2_TOTAL, g_s2>>>(b_enc, 0);
    cudaEventRecord(g_evE[0], g_s2);

    for (int g = 0; g < NGRP; g++) {
        if (g + 1 < NGRP) {
            encode_kernel<<<dim3(H_SZ / 128, ROWG / 128), 256, ESM2_TOTAL, g_s2>>>(
                b_enc, (g + 1) * ROWG);
            cudaEventRecord(g_evE[g + 1], g_s2);
        }
        cudaStreamWaitEvent(0, g_evE[g], 0);
        select_kernel<<<ROWG, 256, SEL_SMEM_BYTES>>>(
            x, W_enc, b_enc, b_dec, W_dec, out, g * ROWG);
    }
    finalize_kernel<<<1, 256>>>(out);
}

// round 14
// speedup vs baseline: 12.8773x; 12.8773x over previous
#include <cuda_runtime.h>
#include <cuda_fp16.h>
#include <cstdint>

#define B_SZ   16384
#define D_SZ   256
#define H_SZ   8192
#define K_TOP  32
#define CAND_K   36     // min candidates needed at chosen threshold
#define CAND_MAX 640    // hit cap (max expected ~440+5sigma for largest-norm rows)
#define TK_MARGIN 4     // ulp margin below chosen threshold
#define ROWG   4096
#define NGRP   (B_SZ / ROWG)
#define HIT_T0 1.9f     // encoder-side hit filter; s32_row >= 2.26 for min-norm rows

// select staging
#define RS_BATCH 16
#define RS_PITCH 260
#define SEL_SMEM_FLOATS (256 + CAND_MAX + CAND_MAX + RS_BATCH * RS_PITCH)
#define SEL_SMEM_BYTES  (SEL_SMEM_FLOATS * 4)

// ---------------------------------------------------------------------------
// Scratch
// ---------------------------------------------------------------------------
__device__ __half g_xh [B_SZ * D_SZ];                 // fp16(x - b_dec)
__device__ __half g_weh[H_SZ * D_SZ];                 // fp16(W_enc)
__device__ uint32_t g_hits[(size_t)B_SZ * CAND_MAX];  // (fp16val<<16)|idx
__device__ int   g_hcnt[B_SZ];
__device__ int   g_counts[H_SZ];
__device__ float g_colsum[64 * D_SZ];
__device__ float g_qpart[64];
__device__ float g_e2part[B_SZ];

// ---------------------------------------------------------------------------
// Helpers
// ---------------------------------------------------------------------------
__device__ __forceinline__ uint32_t smem_u32(const void* p) {
    uint32_t a;
    asm("{ .reg .u64 t; cvta.to.shared.u64 t, %1; cvt.u32.u64 %0, t; }" : "=r"(a) : "l"(p));
    return a;
}
#define CP_ASYNC16(dst, src) \
    asm volatile("cp.async.cg.shared.global [%0], [%1], 16;" :: "r"(dst), "l"(src))
#define CP_COMMIT() asm volatile("cp.async.commit_group;")
#define CP_WAIT(n)  asm volatile("cp.async.wait_group %0;" :: "n"(n))

__device__ __forceinline__ void ldsm_x4(uint32_t& r0, uint32_t& r1, uint32_t& r2, uint32_t& r3,
                                        uint32_t addr) {
    asm volatile("ldmatrix.sync.aligned.m8n8.x4.shared.b16 {%0,%1,%2,%3}, [%4];"
                 : "=r"(r0), "=r"(r1), "=r"(r2), "=r"(r3) : "r"(addr));
}
__device__ __forceinline__ void mma_16816(float* c, uint32_t a0, uint32_t a1, uint32_t a2,
                                          uint32_t a3, uint32_t b0, uint32_t b1) {
    asm volatile(
        "mma.sync.aligned.m16n8k16.row.col.f32.f16.f16.f32 "
        "{%0,%1,%2,%3}, {%4,%5,%6,%7}, {%8,%9}, {%0,%1,%2,%3};"
        : "+f"(c[0]), "+f"(c[1]), "+f"(c[2]), "+f"(c[3])
        : "r"(a0), "r"(a1), "r"(a2), "r"(a3), "r"(b0), "r"(b1));
}
__device__ __forceinline__ void emit_hit(int row, int hcol, float v) {
    int p = atomicAdd(&g_hcnt[row], 1);
    if (p < CAND_MAX) {
        uint32_t pk = ((uint32_t)__half_as_ushort(__float2half_rn(v)) << 16) | (uint32_t)hcol;
        g_hits[(size_t)row * CAND_MAX + p] = pk;
    }
}

// ---------------------------------------------------------------------------
// Kernel 0: convert x -> fp16(x - b_dec), W_enc -> fp16
// ---------------------------------------------------------------------------
__global__ __launch_bounds__(256) void conv_kernel(
    const float* __restrict__ x, const float* __restrict__ W_enc,
    const float* __restrict__ b_dec)
{
    int b = blockIdx.x, t = threadIdx.x;
    if (b < 2048) {
        size_t e0 = ((size_t)b * 256 + t) * 8;
        int col = (int)(e0 & (D_SZ - 1));
        float4 v0 = *(const float4*)(x + e0);
        float4 v1 = *(const float4*)(x + e0 + 4);
        float4 d0 = *(const float4*)(b_dec + col);
        float4 d1 = *(const float4*)(b_dec + col + 4);
        __half o[8];
        o[0]=__float2half_rn(v0.x-d0.x); o[1]=__float2half_rn(v0.y-d0.y);
        o[2]=__float2half_rn(v0.z-d0.z); o[3]=__float2half_rn(v0.w-d0.w);
        o[4]=__float2half_rn(v1.x-d1.x); o[5]=__float2half_rn(v1.y-d1.y);
        o[6]=__float2half_rn(v1.z-d1.z); o[7]=__float2half_rn(v1.w-d1.w);
        *(uint4*)(g_xh + e0) = *(uint4*)o;
    } else {
        size_t e0 = ((size_t)(b - 2048) * 256 + t) * 8;
        float4 v0 = *(const float4*)(W_enc + e0);
        float4 v1 = *(const float4*)(W_enc + e0 + 4);
        __half o[8];
        o[0]=__float2half_rn(v0.x); o[1]=__float2half_rn(v0.y);
        o[2]=__float2half_rn(v0.z); o[3]=__float2half_rn(v0.w);
        o[4]=__float2half_rn(v1.x); o[5]=__float2half_rn(v1.y);
        o[6]=__float2half_rn(v1.z); o[7]=__float2half_rn(v1.w);
        *(uint4*)(g_weh + e0) = *(uint4*)o;
    }
}

// ---------------------------------------------------------------------------
// Kernel 1: column stats of x + zero counts + zero hit counters
// ---------------------------------------------------------------------------
__global__ __launch_bounds__(256) void colstat_kernel(const float* __restrict__ x)
{
    __shared__ float red[256];
    int g = blockIdx.x, t = threadIdx.x;
    int gid = g * 256 + t;
    if (gid < H_SZ) g_counts[gid] = 0;
    g_hcnt[gid] = 0;
    const float* xb = x + (size_t)(g * 256) * D_SZ;
    float s = 0.f, q = 0.f;
    #pragma unroll 8
    for (int r = 0; r < 256; r++) {
        float v = xb[r * D_SZ + t];
        s += v; q += v * v;
    }
    g_colsum[g * D_SZ + t] = s;
    red[t] = q; __syncthreads();
    for (int sft = 128; sft > 0; sft >>= 1) { if (t < sft) red[t] += red[t + sft]; __syncthreads(); }
    if (t == 0) g_qpart[g] = red[0];
}

// ---------------------------------------------------------------------------
// Kernel 2: encoder GEMM via mma.sync; epilogue emits hits (>= HIT_T0).
// ---------------------------------------------------------------------------
#define KC2      64
#define PITCH2   72
#define STG2     (128 * PITCH2 * 2)
#define OFF2_A(p) ((p) * STG2)
#define OFF2_B(p) (2 * STG2 + (p) * STG2)
#define OFF2_BES (4 * STG2)
#define ESM2_TOTAL (OFF2_BES + 512)

__global__ __launch_bounds__(256, 2) void encode_kernel(const float* __restrict__ b_enc,
                                                        int rgBase)
{
    extern __shared__ char smem[];
    const uint32_t sbase = smem_u32(smem);
    const int t = threadIdx.x;
    const int wid = t >> 5, lane = t & 31;
    const int h0 = blockIdx.x * 128;
    const int r0 = rgBase + blockIdx.y * 128;

    const int wm = wid >> 2, wn = wid & 3;
    const int m0w = wm * 64, n0w = wn * 32;

    const char* gA = (const char*)(g_xh  + (size_t)r0 * D_SZ);
    const char* gB = (const char*)(g_weh + (size_t)h0 * D_SZ);

    auto load_stage = [&](int s, int p) {
        #pragma unroll
        for (int i = 0; i < 4; i++) {
            int idx = t + 256 * i;
            int row = idx >> 3, q = idx & 7;
            uint32_t dOff = (uint32_t)((row * PITCH2 + q * 8) * 2);
            size_t gOff = ((size_t)row * D_SZ + s * KC2 + q * 8) * 2;
            CP_ASYNC16(sbase + OFF2_A(p) + dOff, gA + gOff);
            CP_ASYNC16(sbase + OFF2_B(p) + dOff, gB + gOff);
        }
        CP_COMMIT();
    };

    load_stage(0, 0);
    load_stage(1, 1);
    ((float*)(smem + OFF2_BES))[t & 127] = b_enc[h0 + (t & 127)];

    float acc[16][4];
    #pragma unroll
    for (int f = 0; f < 16; f++)
        #pragma unroll
        for (int e = 0; e < 4; e++) acc[f][e] = 0.f;

    const int aRow = lane & 15;
    const int aCol = (lane >> 4) << 3;
    const int bRow = ((lane >> 4) << 3) + (lane & 7);
    const int bCol = ((lane >> 3) & 1) << 3;

    CP_WAIT(1);
    __syncthreads();

    #pragma unroll
    for (int s = 0; s < 4; s++) {
        const int p = s & 1;
        const uint32_t aBase = sbase + OFF2_A(p) + ((m0w + aRow) * PITCH2 + aCol) * 2;
        const uint32_t bBase = sbase + OFF2_B(p) + ((n0w + bRow) * PITCH2 + bCol) * 2;
        #pragma unroll
        for (int k0 = 0; k0 < KC2; k0 += 16) {
            uint32_t a[4][4], b[2][4];
            #pragma unroll
            for (int i = 0; i < 4; i++)
                ldsm_x4(a[i][0], a[i][1], a[i][2], a[i][3],
                        aBase + (i * 16 * PITCH2 + k0) * 2);
            #pragma unroll
            for (int jp = 0; jp < 2; jp++)
                ldsm_x4(b[jp][0], b[jp][1], b[jp][2], b[jp][3],
                        bBase + (jp * 16 * PITCH2 + k0) * 2);
            #pragma unroll
            for (int i = 0; i < 4; i++)
                #pragma unroll
                for (int j = 0; j < 4; j++)
                    mma_16816(acc[i * 4 + j], a[i][0], a[i][1], a[i][2], a[i][3],
                              b[j >> 1][(j & 1) * 2], b[j >> 1][(j & 1) * 2 + 1]);
        }
        if (s < 2) {
            __syncthreads();
            load_stage(s + 2, p);
            CP_WAIT(1);
            __syncthreads();
        } else if (s == 2) {
            CP_WAIT(0);
            __syncthreads();
        }
    }

    // epilogue: bias + hit emission straight from registers
    const float* bes = (const float*)(smem + OFF2_BES);
    const int qr = lane >> 2, qc = lane & 3;
    #pragma unroll
    for (int i = 0; i < 4; i++) {
        #pragma unroll
        for (int j = 0; j < 4; j++) {
            int col = n0w + j * 8 + qc * 2;
            float b0 = bes[col], b1 = bes[col + 1];
            const float* c = acc[i * 4 + j];
            int mA = m0w + i * 16 + qr;
            float v0 = c[0] + b0, v1 = c[1] + b1;
            float v2 = c[2] + b0, v3 = c[3] + b1;
            int rA = r0 + mA, rB = r0 + mA + 8;
            if (v0 >= HIT_T0) emit_hit(rA, h0 + col,     v0);
            if (v1 >= HIT_T0) emit_hit(rA, h0 + col + 1, v1);
            if (v2 >= HIT_T0) emit_hit(rB, h0 + col,     v2);
            if (v3 >= HIT_T0) emit_hit(rB, h0 + col + 1, v3);
        }
    }
}

// ---------------------------------------------------------------------------
// Kernel 3: select+decode from hit lists (<=640 hits, 3 per thread).
// Probe fixed grid, require count >= CAND_K at chosen T (else exact fallback).
// Rescore/rank/decode arithmetic verbatim from passing config.
// ---------------------------------------------------------------------------
__global__ __launch_bounds__(256, 8) void select_kernel(
    const float* __restrict__ x, const float* __restrict__ W_enc,
    const float* __restrict__ b_enc, const float* __restrict__ b_dec,
    const float* __restrict__ W_dec, float* __restrict__ out,
    int rgBase)
{
    extern __shared__ float sm[];
    float* xs  = sm;                       // [256]
    float* cv  = sm + 256;                 // [CAND_MAX]
    int*   ci  = (int*)(sm + 256 + CAND_MAX);
    float* stg = sm + 256 + 2 * CAND_MAX;  // [RS_BATCH][RS_PITCH]; reused as red buf
    __shared__ int cw8[8][8];
    __shared__ int tot[8];
    __shared__ int s_cnt;
    __shared__ float rv[K_TOP];
    __shared__ int   ri[K_TOP];

    const int row = rgBase + blockIdx.x;
    const int t = threadIdx.x, wid = t >> 5, lane = t & 31;

    const float xv  = x[(size_t)row * D_SZ + t];
    const float bdv = b_dec[t];
    xs[t] = xv - bdv;
    if (t == 0) s_cnt = 0;

    const int cntraw = g_hcnt[row];
    const int cntc   = (cntraw < CAND_MAX) ? cntraw : CAND_MAX;

    uint32_t hv[3], hx[3];
    #pragma unroll
    for (int s = 0; s < 3; s++) {
        int p = t + 256 * s;
        hv[s] = 0; hx[s] = 0;
        if (p < cntc) {
            uint32_t pk = g_hits[(size_t)row * CAND_MAX + p];
            hv[s] = pk >> 16;
            hx[s] = pk & 0xFFFFu;
        }
    }

    // probe fixed grid 2.1..2.8 on hit values (one barrier)
    const uint32_t TG[8] = {0x4033,0x4066,0x4099,0x40CD,0x4100,0x4133,0x4166,0x419A};
    #pragma unroll
    for (int j = 0; j < 8; j++) {
        int lc = (hv[0] >= TG[j]) + (hv[1] >= TG[j]) + (hv[2] >= TG[j]);
        unsigned r = __reduce_add_sync(0xffffffffu, (unsigned)lc);
        if (lane == 0) cw8[wid][j] = (int)r;
    }
    __syncthreads();
    if (t < 8) {
        int s = 0;
        #pragma unroll
        for (int i = 0; i < 8; i++) s += cw8[i][t];
        tot[t] = s;
    }
    __syncthreads();

    const bool fb = (cntraw >= CAND_MAX) || (tot[0] < CAND_K);  // uniform per block

    if (!fb) {
        int T = (int)TG[0];
        #pragma unroll
        for (int j = 7; j >= 1; j--) {
            if (tot[j] >= CAND_K) { T = (int)TG[j]; break; }
        }
        const uint32_t Tc = (uint32_t)(T - TK_MARGIN);
        #pragma unroll
        for (int s = 0; s < 3; s++) {
            if (hv[s] >= Tc) {
                int p = atomicAdd(&s_cnt, 1);
                if (p < CAND_MAX) ci[p] = (int)hx[s];
            }
        }
        __syncthreads();
    } else {
        // exact fallback: recompute all H scores, adaptive threshold (rare)
        float thr = HIT_T0;
        for (int iter = 0; iter < 12; iter++) {
            if (t == 0) s_cnt = 0;
            __syncthreads();
            #pragma unroll 1
            for (int i = 0; i < H_SZ / 256; i++) {
                int idx = t + 256 * i;
                const float* wr = W_enc + (size_t)idx * D_SZ;
                float s = 0.f;
                #pragma unroll 8
                for (int k = 0; k < D_SZ; k++) s = fmaf(xs[k], __ldg(&wr[k]), s);
                s = fmaxf(s + b_enc[idx], 0.f);
                if (s >= thr) {
                    int p = atomicAdd(&s_cnt, 1);
                    if (p < CAND_MAX) ci[p] = idx;
                }
            }
            __syncthreads();
            int c = s_cnt;
            if (c >= CAND_K && c < CAND_MAX) break;
            thr = (c >= CAND_MAX) ? thr + 0.3f : thr - 0.4f;
            __syncthreads();
        }
    }
    const int cnt = (s_cnt < CAND_MAX) ? s_cnt : CAND_MAX;

    // rescore: staged coalesced, verbatim sequential fmaf chain
    for (int b0 = 0; b0 < cnt; b0 += RS_BATCH) {
        int nb = min(RS_BATCH, cnt - b0);
        for (int j = t; j < nb * 64; j += 256) {
            int r = j >> 6, c4 = j & 63;
            int idx = ci[b0 + r];
            float4 v = __ldg((const float4*)(W_enc + (size_t)idx * D_SZ) + c4);
            *(float4*)(stg + r * RS_PITCH + c4 * 4) = v;
        }
        __syncthreads();
        if (t < nb) {
            int idx = ci[b0 + t];
            const float* wrow = stg + t * RS_PITCH;
            float s = 0.f;
            #pragma unroll 8
            for (int k = 0; k < D_SZ; k++) s = fmaf(xs[k], wrow[k], s);
            cv[b0 + t] = fmaxf(s + b_enc[idx], 0.f);
        }
        __syncthreads();
    }

    // rank -> top-32 (value desc, index asc) + counts; each thread ranks <=3
    if (t < K_TOP) { rv[t] = 0.f; ri[t] = 0; }
    __syncthreads();
    #pragma unroll
    for (int s = 0; s < 3; s++) {
        int c = t + 256 * s;
        if (c < cnt) {
            float v = cv[c]; int id = ci[c];
            int rank = 0;
            for (int j = 0; j < cnt; j++) {
                float vo = cv[j];
                rank += (vo > v) || (vo == v && ci[j] < id);
            }
            if (rank < K_TOP) {
                rv[rank] = v;
                ri[rank] = id;
                atomicAdd(&g_counts[id], 1);
            }
        }
    }
    __syncthreads();

    // decode column t (identical arithmetic/order to prior decode)
    float acc = bdv;
    #pragma unroll
    for (int j = 0; j < K_TOP; j++)
        acc += rv[j] * __ldg(&W_dec[(size_t)ri[j] * D_SZ + t]);
    out[(size_t)row * D_SZ + t] = acc;

    float e = acc - xv;
    stg[t] = e * e;
    __syncthreads();
    for (int s = 128; s > 0; s >>= 1) {
        if (t < s) stg[t] += stg[t + s];
        __syncthreads();
    }
    if (t == 0) g_e2part[row] = stg[0];
}

// ---------------------------------------------------------------------------
// Kernel 4: finalize
// ---------------------------------------------------------------------------
__global__ __launch_bounds__(256) void finalize_kernel(float* __restrict__ out)
{
    __shared__ float red[256];
    __shared__ float sh_var, sh_q, sh_e2;
    int t = threadIdx.x;
    float S = 0.f;
    for (int g = 0; g < 64; g++) S += g_colsum[g * D_SZ + t];
    red[t] = S * S * (1.0f / (float)B_SZ);
    __syncthreads();
    for (int s = 128; s > 0; s >>= 1) { if (t < s) red[t] += red[t + s]; __syncthreads(); }
    if (t == 0) sh_var = red[0];
    __syncthreads();
    red[t] = (t < 64) ? g_qpart[t] : 0.f;
    __syncthreads();
    for (int s = 128; s > 0; s >>= 1) { if (t < s) red[t] += red[t + s]; __syncthreads(); }
    if (t == 0) sh_q = red[0];
    __syncthreads();
    float e2 = 0.f;
    for (int i = t; i < B_SZ; i += 256) e2 += g_e2part[i];
    red[t] = e2; __syncthreads();
    for (int s = 128; s > 0; s >>= 1) { if (t < s) red[t] += red[t + s]; __syncthreads(); }
    if (t == 0) sh_e2 = red[0];
    __syncthreads();
    if (t == 0) {
        float total_var = sh_q - sh_var;
        out[(size_t)B_SZ * D_SZ + H_SZ] = sh_e2 / total_var;
    }
    for (int i = t; i < H_SZ; i += 256)
        out[(size_t)B_SZ * D_SZ + i] = (float)g_counts[i];
}

// ---------------------------------------------------------------------------
// Launch: encode on second stream, overlapped with select of prior group.
// ---------------------------------------------------------------------------
static cudaStream_t g_s2 = nullptr;
static cudaEvent_t  g_evC = nullptr;
static cudaEvent_t  g_evE[NGRP];

extern "C" void kernel_launch(void* const* d_in, const int* in_sizes, int n_in,
                              void* d_out, int out_size)
{
    const float* x     = (const float*)d_in[0];
    const float* W_enc = (const float*)d_in[1];
    const float* b_enc = (const float*)d_in[2];
    const float* W_dec = (const float*)d_in[3];
    const float* b_dec = (const float*)d_in[4];
    float* out = (float*)d_out;

    if (g_s2 == nullptr) {
        cudaStreamCreateWithFlags(&g_s2, cudaStreamNonBlocking);
        cudaEventCreateWithFlags(&g_evC, cudaEventDisableTiming);
        for (int g = 0; g < NGRP; g++)
            cudaEventCreateWithFlags(&g_evE[g], cudaEventDisableTiming);
        cudaFuncSetAttribute(encode_kernel,
                             cudaFuncAttributeMaxDynamicSharedMemorySize, ESM2_TOTAL);
        cudaFuncSetAttribute(select_kernel,
                             cudaFuncAttributeMaxDynamicSharedMemorySize, SEL_SMEM_BYTES);
    }

    conv_kernel<<<3072, 256>>>(x, W_enc, b_dec);
    colstat_kernel<<<64, 256>>>(x);
    cudaEventRecord(g_evC, 0);
    cudaStreamWaitEvent(g_s2, g_evC, 0);

    encode_kernel<<<dim3(H_SZ / 128, ROWG / 128), 256, ESM2_TOTAL, g_s2>>>(b_enc, 0);
    cudaEventRecord(g_evE[0], g_s2);

    for (int g = 0; g < NGRP; g++) {
        if (g + 1 < NGRP) {
            encode_kernel<<<dim3(H_SZ / 128, ROWG / 128), 256, ESM2_TOTAL, g_s2>>>(
                b_enc, (g + 1) * ROWG);
            cudaEventRecord(g_evE[g + 1], g_s2);
        }
        cudaStreamWaitEvent(0, g_evE[g], 0);
        select_kernel<<<ROWG, 256, SEL_SMEM_BYTES>>>(
            x, W_enc, b_enc, b_dec, W_dec, out, g * ROWG);
    }
    finalize_kernel<<<1, 256>>>(out);
}

// round 15
// speedup vs baseline: 15.6157x; 1.2127x over previous
#include <cuda_runtime.h>
#include <cuda_fp16.h>
#include <cstdint>

#define B_SZ   16384
#define D_SZ   256
#define H_SZ   8192
#define K_TOP  32
#define CAND_K   36     // min candidates needed at chosen grid threshold
#define CAND_MAX 256    // hit cap (mean 100, +15sigma Poisson safe)
#define TK_MARGIN 4     // fp16-ulp margin below chosen threshold
#define ROWG   4096
#define NGRP   (B_SZ / ROWG)
#define THR_MULT 2.25f  // per-row threshold = THR_MULT * ||x-b_dec|| / 16

// select staging
#define RS_BATCH 16
#define RS_PITCH 260
#define SEL_SMEM_FLOATS (256 + CAND_MAX + CAND_MAX + RS_BATCH * RS_PITCH)
#define SEL_SMEM_BYTES  (SEL_SMEM_FLOATS * 4)

// ---------------------------------------------------------------------------
// Scratch
// ---------------------------------------------------------------------------
__device__ __half g_xh [B_SZ * D_SZ];                 // fp16(x - b_dec)
__device__ __half g_weh[H_SZ * D_SZ];                 // fp16(W_enc)
__device__ uint32_t g_hits[(size_t)B_SZ * CAND_MAX];  // (fp16val<<16)|idx
__device__ int   g_hcnt[B_SZ];
__device__ float g_rthr[B_SZ];                        // per-row hit threshold
__device__ int   g_counts[H_SZ];
__device__ float g_colsum[64 * D_SZ];
__device__ float g_qpart[64];
__device__ float g_e2part[B_SZ];

// ---------------------------------------------------------------------------
// Helpers
// ---------------------------------------------------------------------------
__device__ __forceinline__ uint32_t smem_u32(const void* p) {
    uint32_t a;
    asm("{ .reg .u64 t; cvta.to.shared.u64 t, %1; cvt.u32.u64 %0, t; }" : "=r"(a) : "l"(p));
    return a;
}
#define CP_ASYNC16(dst, src) \
    asm volatile("cp.async.cg.shared.global [%0], [%1], 16;" :: "r"(dst), "l"(src))
#define CP_COMMIT() asm volatile("cp.async.commit_group;")
#define CP_WAIT(n)  asm volatile("cp.async.wait_group %0;" :: "n"(n))

__device__ __forceinline__ void ldsm_x4(uint32_t& r0, uint32_t& r1, uint32_t& r2, uint32_t& r3,
                                        uint32_t addr) {
    asm volatile("ldmatrix.sync.aligned.m8n8.x4.shared.b16 {%0,%1,%2,%3}, [%4];"
                 : "=r"(r0), "=r"(r1), "=r"(r2), "=r"(r3) : "r"(addr));
}
__device__ __forceinline__ void mma_16816(float* c, uint32_t a0, uint32_t a1, uint32_t a2,
                                          uint32_t a3, uint32_t b0, uint32_t b1) {
    asm volatile(
        "mma.sync.aligned.m16n8k16.row.col.f32.f16.f16.f32 "
        "{%0,%1,%2,%3}, {%4,%5,%6,%7}, {%8,%9}, {%0,%1,%2,%3};"
        : "+f"(c[0]), "+f"(c[1]), "+f"(c[2]), "+f"(c[3])
        : "r"(a0), "r"(a1), "r"(a2), "r"(a3), "r"(b0), "r"(b1));
}
__device__ __forceinline__ void emit_hit(int row, int hcol, float v) {
    int p = atomicAdd(&g_hcnt[row], 1);
    if (p < CAND_MAX) {
        uint32_t pk = ((uint32_t)__half_as_ushort(__float2half_rn(v)) << 16) | (uint32_t)hcol;
        g_hits[(size_t)row * CAND_MAX + p] = pk;
    }
}

// ---------------------------------------------------------------------------
// Kernel 0: convert x -> fp16(x - b_dec), W_enc -> fp16
// ---------------------------------------------------------------------------
__global__ __launch_bounds__(256) void conv_kernel(
    const float* __restrict__ x, const float* __restrict__ W_enc,
    const float* __restrict__ b_dec)
{
    int b = blockIdx.x, t = threadIdx.x;
    if (b < 2048) {
        size_t e0 = ((size_t)b * 256 + t) * 8;
        int col = (int)(e0 & (D_SZ - 1));
        float4 v0 = *(const float4*)(x + e0);
        float4 v1 = *(const float4*)(x + e0 + 4);
        float4 d0 = *(const float4*)(b_dec + col);
        float4 d1 = *(const float4*)(b_dec + col + 4);
        __half o[8];
        o[0]=__float2half_rn(v0.x-d0.x); o[1]=__float2half_rn(v0.y-d0.y);
        o[2]=__float2half_rn(v0.z-d0.z); o[3]=__float2half_rn(v0.w-d0.w);
        o[4]=__float2half_rn(v1.x-d1.x); o[5]=__float2half_rn(v1.y-d1.y);
        o[6]=__float2half_rn(v1.z-d1.z); o[7]=__float2half_rn(v1.w-d1.w);
        *(uint4*)(g_xh + e0) = *(uint4*)o;
    } else {
        size_t e0 = ((size_t)(b - 2048) * 256 + t) * 8;
        float4 v0 = *(const float4*)(W_enc + e0);
        float4 v1 = *(const float4*)(W_enc + e0 + 4);
        __half o[8];
        o[0]=__float2half_rn(v0.x); o[1]=__float2half_rn(v0.y);
        o[2]=__float2half_rn(v0.z); o[3]=__float2half_rn(v0.w);
        o[4]=__float2half_rn(v1.x); o[5]=__float2half_rn(v1.y);
        o[6]=__float2half_rn(v1.z); o[7]=__float2half_rn(v1.w);
        *(uint4*)(g_weh + e0) = *(uint4*)o;
    }
}

// ---------------------------------------------------------------------------
// Kernel 0b: per-row threshold = THR_MULT * ||x - b_dec|| / 16 (warp per row)
// ---------------------------------------------------------------------------
__global__ __launch_bounds__(256) void rowstat_kernel()
{
    int row = blockIdx.x * 8 + (threadIdx.x >> 5);
    int lane = threadIdx.x & 31;
    const __half2* xr = (const __half2*)(g_xh + (size_t)row * D_SZ);
    float s = 0.f;
    #pragma unroll
    for (int i = 0; i < 4; i++) {
        float2 v = __half22float2(xr[lane + 32 * i]);
        s += v.x * v.x + v.y * v.y;
    }
    #pragma unroll
    for (int off = 16; off > 0; off >>= 1) s += __shfl_down_sync(0xffffffffu, s, off);
    if (lane == 0) g_rthr[row] = THR_MULT * sqrtf(s) * (1.0f / 16.0f);
}

// ---------------------------------------------------------------------------
// Kernel 1: column stats of x + zero counts + zero hit counters
// ---------------------------------------------------------------------------
__global__ __launch_bounds__(256) void colstat_kernel(const float* __restrict__ x)
{
    __shared__ float red[256];
    int g = blockIdx.x, t = threadIdx.x;
    int gid = g * 256 + t;
    if (gid < H_SZ) g_counts[gid] = 0;
    g_hcnt[gid] = 0;
    const float* xb = x + (size_t)(g * 256) * D_SZ;
    float s = 0.f, q = 0.f;
    #pragma unroll 8
    for (int r = 0; r < 256; r++) {
        float v = xb[r * D_SZ + t];
        s += v; q += v * v;
    }
    g_colsum[g * D_SZ + t] = s;
    red[t] = q; __syncthreads();
    for (int sft = 128; sft > 0; sft >>= 1) { if (t < sft) red[t] += red[t + sft]; __syncthreads(); }
    if (t == 0) g_qpart[g] = red[0];
}

// ---------------------------------------------------------------------------
// Kernel 2: encoder GEMM via mma.sync; epilogue emits hits (>= per-row thr).
// ---------------------------------------------------------------------------
#define KC2      64
#define PITCH2   72
#define STG2     (128 * PITCH2 * 2)
#define OFF2_A(p) ((p) * STG2)
#define OFF2_B(p) (2 * STG2 + (p) * STG2)
#define OFF2_BES (4 * STG2)
#define ESM2_TOTAL (OFF2_BES + 512)

__global__ __launch_bounds__(256, 2) void encode_kernel(const float* __restrict__ b_enc,
                                                        int rgBase)
{
    extern __shared__ char smem[];
    const uint32_t sbase = smem_u32(smem);
    const int t = threadIdx.x;
    const int wid = t >> 5, lane = t & 31;
    const int h0 = blockIdx.x * 128;
    const int r0 = rgBase + blockIdx.y * 128;

    const int wm = wid >> 2, wn = wid & 3;
    const int m0w = wm * 64, n0w = wn * 32;

    const char* gA = (const char*)(g_xh  + (size_t)r0 * D_SZ);
    const char* gB = (const char*)(g_weh + (size_t)h0 * D_SZ);

    auto load_stage = [&](int s, int p) {
        #pragma unroll
        for (int i = 0; i < 4; i++) {
            int idx = t + 256 * i;
            int row = idx >> 3, q = idx & 7;
            uint32_t dOff = (uint32_t)((row * PITCH2 + q * 8) * 2);
            size_t gOff = ((size_t)row * D_SZ + s * KC2 + q * 8) * 2;
            CP_ASYNC16(sbase + OFF2_A(p) + dOff, gA + gOff);
            CP_ASYNC16(sbase + OFF2_B(p) + dOff, gB + gOff);
        }
        CP_COMMIT();
    };

    load_stage(0, 0);
    load_stage(1, 1);
    ((float*)(smem + OFF2_BES))[t & 127] = b_enc[h0 + (t & 127)];

    float acc[16][4];
    #pragma unroll
    for (int f = 0; f < 16; f++)
        #pragma unroll
        for (int e = 0; e < 4; e++) acc[f][e] = 0.f;

    const int aRow = lane & 15;
    const int aCol = (lane >> 4) << 3;
    const int bRow = ((lane >> 4) << 3) + (lane & 7);
    const int bCol = ((lane >> 3) & 1) << 3;

    CP_WAIT(1);
    __syncthreads();

    #pragma unroll
    for (int s = 0; s < 4; s++) {
        const int p = s & 1;
        const uint32_t aBase = sbase + OFF2_A(p) + ((m0w + aRow) * PITCH2 + aCol) * 2;
        const uint32_t bBase = sbase + OFF2_B(p) + ((n0w + bRow) * PITCH2 + bCol) * 2;
        #pragma unroll
        for (int k0 = 0; k0 < KC2; k0 += 16) {
            uint32_t a[4][4], b[2][4];
            #pragma unroll
            for (int i = 0; i < 4; i++)
                ldsm_x4(a[i][0], a[i][1], a[i][2], a[i][3],
                        aBase + (i * 16 * PITCH2 + k0) * 2);
            #pragma unroll
            for (int jp = 0; jp < 2; jp++)
                ldsm_x4(b[jp][0], b[jp][1], b[jp][2], b[jp][3],
                        bBase + (jp * 16 * PITCH2 + k0) * 2);
            #pragma unroll
            for (int i = 0; i < 4; i++)
                #pragma unroll
                for (int j = 0; j < 4; j++)
                    mma_16816(acc[i * 4 + j], a[i][0], a[i][1], a[i][2], a[i][3],
                              b[j >> 1][(j & 1) * 2], b[j >> 1][(j & 1) * 2 + 1]);
        }
        if (s < 2) {
            __syncthreads();
            load_stage(s + 2, p);
            CP_WAIT(1);
            __syncthreads();
        } else if (s == 2) {
            CP_WAIT(0);
            __syncthreads();
        }
    }

    // epilogue: bias + per-row-threshold hit emission straight from registers
    const float* bes = (const float*)(smem + OFF2_BES);
    const int qr = lane >> 2, qc = lane & 3;
    #pragma unroll
    for (int i = 0; i < 4; i++) {
        int mA = m0w + i * 16 + qr;
        int rA = r0 + mA, rB = rA + 8;
        float thrA = __ldg(&g_rthr[rA]);
        float thrB = __ldg(&g_rthr[rB]);
        #pragma unroll
        for (int j = 0; j < 4; j++) {
            int col = n0w + j * 8 + qc * 2;
            float b0 = bes[col], b1 = bes[col + 1];
            const float* c = acc[i * 4 + j];
            float v0 = c[0] + b0, v1 = c[1] + b1;
            float v2 = c[2] + b0, v3 = c[3] + b1;
            if (v0 >= thrA) emit_hit(rA, h0 + col,     v0);
            if (v1 >= thrA) emit_hit(rA, h0 + col + 1, v1);
            if (v2 >= thrB) emit_hit(rB, h0 + col,     v2);
            if (v3 >= thrB) emit_hit(rB, h0 + col + 1, v3);
        }
    }
}

// ---------------------------------------------------------------------------
// Kernel 3: select+decode from hit lists (<=256 hits, 1 per thread).
// Per-row multiplicative grid probe; collect >= T-4ulp; exact staged rescore
// (verbatim sequential fmaf); rank; decode + counts + e^2.
// ---------------------------------------------------------------------------
__global__ __launch_bounds__(256, 8) void select_kernel(
    const float* __restrict__ x, const float* __restrict__ W_enc,
    const float* __restrict__ b_enc, const float* __restrict__ b_dec,
    const float* __restrict__ W_dec, float* __restrict__ out,
    int rgBase)
{
    extern __shared__ float sm[];
    float* xs  = sm;                       // [256]
    float* cv  = sm + 256;                 // [CAND_MAX]
    int*   ci  = (int*)(sm + 256 + CAND_MAX);
    float* stg = sm + 256 + 2 * CAND_MAX;  // [RS_BATCH][RS_PITCH]; reused as red buf
    __shared__ int cw8[8][8];
    __shared__ int tot[8];
    __shared__ int s_cnt;
    __shared__ float rv[K_TOP];
    __shared__ int   ri[K_TOP];

    const int row = rgBase + blockIdx.x;
    const int t = threadIdx.x, wid = t >> 5, lane = t & 31;

    const float xv  = x[(size_t)row * D_SZ + t];
    const float bdv = b_dec[t];
    xs[t] = xv - bdv;
    if (t == 0) s_cnt = 0;

    const int cntraw = g_hcnt[row];
    const int cntc   = (cntraw < CAND_MAX) ? cntraw : CAND_MAX;
    const float thr  = g_rthr[row];

    uint32_t hv = 0, hx = 0;
    if (t < cntc) {
        uint32_t pk = g_hits[(size_t)row * CAND_MAX + t];
        hv = pk >> 16;
        hx = pk & 0xFFFFu;
    }

    // per-row multiplicative probe grid (8 points, one barrier)
    const float FM[8] = {1.00f,1.05f,1.10f,1.15f,1.20f,1.25f,1.30f,1.35f};
    uint32_t TG[8];
    #pragma unroll
    for (int j = 0; j < 8; j++)
        TG[j] = (uint32_t)__half_as_ushort(__float2half_rn(thr * FM[j]));
    #pragma unroll
    for (int j = 0; j < 8; j++) {
        unsigned r = __reduce_add_sync(0xffffffffu, (unsigned)(t < cntc && hv >= TG[j]));
        if (lane == 0) cw8[wid][j] = (int)r;
    }
    __syncthreads();
    if (t < 8) {
        int s = 0;
        #pragma unroll
        for (int i = 0; i < 8; i++) s += cw8[i][t];
        tot[t] = s;
    }
    __syncthreads();

    const bool fb = (cntraw >= CAND_MAX) || (tot[0] < CAND_K);  // uniform per block

    if (!fb) {
        int T = (int)TG[0];
        #pragma unroll
        for (int j = 7; j >= 1; j--) {
            if (tot[j] >= CAND_K) { T = (int)TG[j]; break; }
        }
        const uint32_t Tc = (uint32_t)(T - TK_MARGIN);
        if (t < cntc && hv >= Tc) {
            int p = atomicAdd(&s_cnt, 1);
            ci[p] = (int)hx;
        }
        __syncthreads();
    } else {
        // exact fallback: recompute all H scores, adaptive threshold (rare)
        float athr = thr;
        for (int iter = 0; iter < 12; iter++) {
            if (t == 0) s_cnt = 0;
            __syncthreads();
            #pragma unroll 1
            for (int i = 0; i < H_SZ / 256; i++) {
                int idx = t + 256 * i;
                const float* wr = W_enc + (size_t)idx * D_SZ;
                float s = 0.f;
                #pragma unroll 8
                for (int k = 0; k < D_SZ; k++) s = fmaf(xs[k], __ldg(&wr[k]), s);
                s = fmaxf(s + b_enc[idx], 0.f);
                if (s >= athr) {
                    int p = atomicAdd(&s_cnt, 1);
                    if (p < CAND_MAX) ci[p] = idx;
                }
            }
            __syncthreads();
            int c = s_cnt;
            if (c >= CAND_K && c < CAND_MAX) break;
            athr = (c >= CAND_MAX) ? athr * 1.12f : athr * 0.85f;
            __syncthreads();
        }
    }
    const int cnt = (s_cnt < CAND_MAX) ? s_cnt : CAND_MAX;

    // rescore: staged coalesced, verbatim sequential fmaf chain
    for (int b0 = 0; b0 < cnt; b0 += RS_BATCH) {
        int nb = min(RS_BATCH, cnt - b0);
        for (int j = t; j < nb * 64; j += 256) {
            int r = j >> 6, c4 = j & 63;
            int idx = ci[b0 + r];
            float4 v = __ldg((const float4*)(W_enc + (size_t)idx * D_SZ) + c4);
            *(float4*)(stg + r * RS_PITCH + c4 * 4) = v;
        }
        __syncthreads();
        if (t < nb) {
            int idx = ci[b0 + t];
            const float* wrow = stg + t * RS_PITCH;
            float s = 0.f;
            #pragma unroll 8
            for (int k = 0; k < D_SZ; k++) s = fmaf(xs[k], wrow[k], s);
            cv[b0 + t] = fmaxf(s + b_enc[idx], 0.f);
        }
        __syncthreads();
    }

    // rank -> top-32 (value desc, index asc) + counts
    if (t < K_TOP) { rv[t] = 0.f; ri[t] = 0; }
    __syncthreads();
    if (t < cnt) {
        float v = cv[t]; int id = ci[t];
        int rank = 0;
        for (int j = 0; j < cnt; j++) {
            float vo = cv[j];
            rank += (vo > v) || (vo == v && ci[j] < id);
        }
        if (rank < K_TOP) {
            rv[rank] = v;
            ri[rank] = id;
            atomicAdd(&g_counts[id], 1);
        }
    }
    __syncthreads();

    // decode column t (identical arithmetic/order to prior decode)
    float acc = bdv;
    #pragma unroll
    for (int j = 0; j < K_TOP; j++)
        acc += rv[j] * __ldg(&W_dec[(size_t)ri[j] * D_SZ + t]);
    out[(size_t)row * D_SZ + t] = acc;

    float e = acc - xv;
    stg[t] = e * e;
    __syncthreads();
    for (int s = 128; s > 0; s >>= 1) {
        if (t < s) stg[t] += stg[t + s];
        __syncthreads();
    }
    if (t == 0) g_e2part[row] = stg[0];
}

// ---------------------------------------------------------------------------
// Kernel 4: finalize
// ---------------------------------------------------------------------------
__global__ __launch_bounds__(256) void finalize_kernel(float* __restrict__ out)
{
    __shared__ float red[256];
    __shared__ float sh_var, sh_q, sh_e2;
    int t = threadIdx.x;
    float S = 0.f;
    for (int g = 0; g < 64; g++) S += g_colsum[g * D_SZ + t];
    red[t] = S * S * (1.0f / (float)B_SZ);
    __syncthreads();
    for (int s = 128; s > 0; s >>= 1) { if (t < s) red[t] += red[t + s]; __syncthreads(); }
    if (t == 0) sh_var = red[0];
    __syncthreads();
    red[t] = (t < 64) ? g_qpart[t] : 0.f;
    __syncthreads();
    for (int s = 128; s > 0; s >>= 1) { if (t < s) red[t] += red[t + s]; __syncthreads(); }
    if (t == 0) sh_q = red[0];
    __syncthreads();
    float e2 = 0.f;
    for (int i = t; i < B_SZ; i += 256) e2 += g_e2part[i];
    red[t] = e2; __syncthreads();
    for (int s = 128; s > 0; s >>= 1) { if (t < s) red[t] += red[t + s]; __syncthreads(); }
    if (t == 0) sh_e2 = red[0];
    __syncthreads();
    if (t == 0) {
        float total_var = sh_q - sh_var;
        out[(size_t)B_SZ * D_SZ + H_SZ] = sh_e2 / total_var;
    }
    for (int i = t; i < H_SZ; i += 256)
        out[(size_t)B_SZ * D_SZ + i] = (float)g_counts[i];
}

// ---------------------------------------------------------------------------
// Launch: encode on second stream, overlapped with select of prior group.
// rowstat precedes encode (thresholds) and select on both streams.
// ---------------------------------------------------------------------------
static cudaStream_t g_s2 = nullptr;
static cudaEvent_t  g_evC = nullptr;
static cudaEvent_t  g_evE[NGRP];

extern "C" void kernel_launch(void* const* d_in, const int* in_sizes, int n_in,
                              void* d_out, int out_size)
{
    const float* x     = (const float*)d_in[0];
    const float* W_enc = (const float*)d_in[1];
    const float* b_enc = (const float*)d_in[2];
    const float* W_dec = (const float*)d_in[3];
    const float* b_dec = (const float*)d_in[4];
    float* out = (float*)d_out;

    if (g_s2 == nullptr) {
        cudaStreamCreateWithFlags(&g_s2, cudaStreamNonBlocking);
        cudaEventCreateWithFlags(&g_evC, cudaEventDisableTiming);
        for (int g = 0; g < NGRP; g++)
            cudaEventCreateWithFlags(&g_evE[g], cudaEventDisableTiming);
        cudaFuncSetAttribute(encode_kernel,
                             cudaFuncAttributeMaxDynamicSharedMemorySize, ESM2_TOTAL);
        cudaFuncSetAttribute(select_kernel,
                             cudaFuncAttributeMaxDynamicSharedMemorySize, SEL_SMEM_BYTES);
    }

    conv_kernel<<<3072, 256>>>(x, W_enc, b_dec);
    rowstat_kernel<<<B_SZ / 8, 256>>>();
    colstat_kernel<<<64, 256>>>(x);
    cudaEventRecord(g_evC, 0);
    cudaStreamWaitEvent(g_s2, g_evC, 0);

    encode_kernel<<<dim3(H_SZ / 128, ROWG / 128), 256, ESM2_TOTAL, g_s2>>>(b_enc, 0);
    cudaEventRecord(g_evE[0], g_s2);

    for (int g = 0; g < NGRP; g++) {
        if (g + 1 < NGRP) {
            encode_kernel<<<dim3(H_SZ / 128, ROWG / 128), 256, ESM2_TOTAL, g_s2>>>(
                b_enc, (g + 1) * ROWG);
            cudaEventRecord(g_evE[g + 1], g_s2);
        }
        cudaStreamWaitEvent(0, g_evE[g], 0);
        select_kernel<<<ROWG, 256, SEL_SMEM_BYTES>>>(
            x, W_enc, b_enc, b_dec, W_dec, out, g * ROWG);
    }
    finalize_kernel<<<1, 256>>>(out);
}

// round 16
// speedup vs baseline: 16.6782x; 1.0680x over previous
#include <cuda_runtime.h>
#include <cuda_fp16.h>
#include <cstdint>

#define B_SZ   16384
#define D_SZ   256
#define H_SZ   8192
#define K_TOP  32
#define CAND_K   36     // min acceptable candidate count at threshold
#define CAND_MAX 96     // candidate buffer cap
#define TK_MARGIN 4     // ulp margin below threshold (covers 2*delta fp16+GEMM err)
#define ROWG   2048     // row-group size (finer pipelining; acts slab 32MB in L2)
#define NGRP   (B_SZ / ROWG)

// select staging — 16-row batches: smem 18.4KB so 8 CTAs/SM fit
#define RS_BATCH 16
#define RS_PITCH 260    // words per staged row (1040B)
#define SEL_SMEM_FLOATS (256 + CAND_MAX + CAND_MAX + RS_BATCH * RS_PITCH)
#define SEL_SMEM_BYTES  (SEL_SMEM_FLOATS * 4)

// ---------------------------------------------------------------------------
// Scratch (__device__ globals)
// ---------------------------------------------------------------------------
__device__ __half g_xh [B_SZ * D_SZ];                 // fp16(x - b_dec)
__device__ __half g_weh[H_SZ * D_SZ];                 // fp16(W_enc)
__device__ __half g_acts[(size_t)B_SZ * H_SZ];        // fp16 relu(pre_acts)
__device__ int   g_counts[H_SZ];
__device__ float g_colsum[64 * D_SZ];
__device__ float g_qpart[64];
__device__ float g_e2part[B_SZ];                      // per-row e^2

// ---------------------------------------------------------------------------
// Helpers
// ---------------------------------------------------------------------------
__device__ __forceinline__ uint32_t smem_u32(const void* p) {
    uint32_t a;
    asm("{ .reg .u64 t; cvta.to.shared.u64 t, %1; cvt.u32.u64 %0, t; }" : "=r"(a) : "l"(p));
    return a;
}
#define CP_ASYNC16(dst, src) \
    asm volatile("cp.async.cg.shared.global [%0], [%1], 16;" :: "r"(dst), "l"(src))
#define CP_COMMIT() asm volatile("cp.async.commit_group;")
#define CP_WAIT(n)  asm volatile("cp.async.wait_group %0;" :: "n"(n))

__device__ __forceinline__ void ldsm_x4(uint32_t& r0, uint32_t& r1, uint32_t& r2, uint32_t& r3,
                                        uint32_t addr) {
    asm volatile("ldmatrix.sync.aligned.m8n8.x4.shared.b16 {%0,%1,%2,%3}, [%4];"
                 : "=r"(r0), "=r"(r1), "=r"(r2), "=r"(r3) : "r"(addr));
}
__device__ __forceinline__ void mma_16816(float* c, uint32_t a0, uint32_t a1, uint32_t a2,
                                          uint32_t a3, uint32_t b0, uint32_t b1) {
    asm volatile(
        "mma.sync.aligned.m16n8k16.row.col.f32.f16.f16.f32 "
        "{%0,%1,%2,%3}, {%4,%5,%6,%7}, {%8,%9}, {%0,%1,%2,%3};"
        : "+f"(c[0]), "+f"(c[1]), "+f"(c[2]), "+f"(c[3])
        : "r"(a0), "r"(a1), "r"(a2), "r"(a3), "r"(b0), "r"(b1));
}

// ---------------------------------------------------------------------------
// Kernel 0: convert x -> fp16(x - b_dec), W_enc -> fp16
// ---------------------------------------------------------------------------
__global__ __launch_bounds__(256) void conv_kernel(
    const float* __restrict__ x, const float* __restrict__ W_enc,
    const float* __restrict__ b_dec)
{
    int b = blockIdx.x, t = threadIdx.x;
    if (b < 2048) {
        size_t e0 = ((size_t)b * 256 + t) * 8;
        int col = (int)(e0 & (D_SZ - 1));
        float4 v0 = *(const float4*)(x + e0);
        float4 v1 = *(const float4*)(x + e0 + 4);
        float4 d0 = *(const float4*)(b_dec + col);
        float4 d1 = *(const float4*)(b_dec + col + 4);
        __half o[8];
        o[0]=__float2half_rn(v0.x-d0.x); o[1]=__float2half_rn(v0.y-d0.y);
        o[2]=__float2half_rn(v0.z-d0.z); o[3]=__float2half_rn(v0.w-d0.w);
        o[4]=__float2half_rn(v1.x-d1.x); o[5]=__float2half_rn(v1.y-d1.y);
        o[6]=__float2half_rn(v1.z-d1.z); o[7]=__float2half_rn(v1.w-d1.w);
        *(uint4*)(g_xh + e0) = *(uint4*)o;
    } else {
        size_t e0 = ((size_t)(b - 2048) * 256 + t) * 8;
        float4 v0 = *(const float4*)(W_enc + e0);
        float4 v1 = *(const float4*)(W_enc + e0 + 4);
        __half o[8];
        o[0]=__float2half_rn(v0.x); o[1]=__float2half_rn(v0.y);
        o[2]=__float2half_rn(v0.z); o[3]=__float2half_rn(v0.w);
        o[4]=__float2half_rn(v1.x); o[5]=__float2half_rn(v1.y);
        o[6]=__float2half_rn(v1.z); o[7]=__float2half_rn(v1.w);
        *(uint4*)(g_weh + e0) = *(uint4*)o;
    }
}

// ---------------------------------------------------------------------------
// Kernel 1: column stats of x + zero counts
// ---------------------------------------------------------------------------
__global__ __launch_bounds__(256) void colstat_kernel(const float* __restrict__ x)
{
    __shared__ float red[256];
    int g = blockIdx.x, t = threadIdx.x;
    int gid = g * 256 + t;
    if (gid < H_SZ) g_counts[gid] = 0;
    const float* xb = x + (size_t)(g * 256) * D_SZ;
    float s = 0.f, q = 0.f;
    #pragma unroll 8
    for (int r = 0; r < 256; r++) {
        float v = xb[r * D_SZ + t];
        s += v; q += v * v;
    }
    g_colsum[g * D_SZ + t] = s;
    red[t] = q; __syncthreads();
    for (int sft = 128; sft > 0; sft >>= 1) { if (t < sft) red[t] += red[t + sft]; __syncthreads(); }
    if (t == 0) g_qpart[g] = red[0];
}

// ---------------------------------------------------------------------------
// Kernel 2: encoder GEMM via mma.sync (fp16 HMMA), 128x128x256 per block.
// K staged in 4 chunks of 64 (2 buffers); smem 74.2KB -> 2 CTAs/SM.
// ---------------------------------------------------------------------------
#define KC2      64
#define PITCH2   72
#define STG2     (128 * PITCH2 * 2)
#define OFF2_A(p) ((p) * STG2)
#define OFF2_B(p) (2 * STG2 + (p) * STG2)
#define OFF2_BES (4 * STG2)
#define ESM2_TOTAL (OFF2_BES + 512)
#define STAGE_PITCH_U32 68

__global__ __launch_bounds__(256, 2) void encode_kernel(const float* __restrict__ b_enc,
                                                        int rgBase)
{
    extern __shared__ char smem[];
    const uint32_t sbase = smem_u32(smem);
    const int t = threadIdx.x;
    const int wid = t >> 5, lane = t & 31;
    const int h0 = blockIdx.x * 128;
    const int r0 = rgBase + blockIdx.y * 128;

    const int wm = wid >> 2, wn = wid & 3;
    const int m0w = wm * 64, n0w = wn * 32;

    const char* gA = (const char*)(g_xh  + (size_t)r0 * D_SZ);
    const char* gB = (const char*)(g_weh + (size_t)h0 * D_SZ);

    auto load_stage = [&](int s, int p) {
        #pragma unroll
        for (int i = 0; i < 4; i++) {
            int idx = t + 256 * i;
            int row = idx >> 3, q = idx & 7;
            uint32_t dOff = (uint32_t)((row * PITCH2 + q * 8) * 2);
            size_t gOff = ((size_t)row * D_SZ + s * KC2 + q * 8) * 2;
            CP_ASYNC16(sbase + OFF2_A(p) + dOff, gA + gOff);
            CP_ASYNC16(sbase + OFF2_B(p) + dOff, gB + gOff);
        }
        CP_COMMIT();
    };

    load_stage(0, 0);
    load_stage(1, 1);
    ((float*)(smem + OFF2_BES))[t & 127] = b_enc[h0 + (t & 127)];

    float acc[16][4];
    #pragma unroll
    for (int f = 0; f < 16; f++)
        #pragma unroll
        for (int e = 0; e < 4; e++) acc[f][e] = 0.f;

    const int aRow = lane & 15;
    const int aCol = (lane >> 4) << 3;
    const int bRow = ((lane >> 4) << 3) + (lane & 7);
    const int bCol = ((lane >> 3) & 1) << 3;

    CP_WAIT(1);
    __syncthreads();

    #pragma unroll
    for (int s = 0; s < 4; s++) {
        const int p = s & 1;
        const uint32_t aBase = sbase + OFF2_A(p) + ((m0w + aRow) * PITCH2 + aCol) * 2;
        const uint32_t bBase = sbase + OFF2_B(p) + ((n0w + bRow) * PITCH2 + bCol) * 2;
        #pragma unroll
        for (int k0 = 0; k0 < KC2; k0 += 16) {
            uint32_t a[4][4], b[2][4];
            #pragma unroll
            for (int i = 0; i < 4; i++)
                ldsm_x4(a[i][0], a[i][1], a[i][2], a[i][3],
                        aBase + (i * 16 * PITCH2 + k0) * 2);
            #pragma unroll
            for (int jp = 0; jp < 2; jp++)
                ldsm_x4(b[jp][0], b[jp][1], b[jp][2], b[jp][3],
                        bBase + (jp * 16 * PITCH2 + k0) * 2);
            #pragma unroll
            for (int i = 0; i < 4; i++)
                #pragma unroll
                for (int j = 0; j < 4; j++)
                    mma_16816(acc[i * 4 + j], a[i][0], a[i][1], a[i][2], a[i][3],
                              b[j >> 1][(j & 1) * 2], b[j >> 1][(j & 1) * 2 + 1]);
        }
        if (s < 2) {
            __syncthreads();
            load_stage(s + 2, p);
            CP_WAIT(1);
            __syncthreads();
        } else if (s == 2) {
            CP_WAIT(0);
            __syncthreads();
        }
    }
    __syncthreads();

    uint32_t* stg = (uint32_t*)smem;
    const float* bes = (const float*)(smem + OFF2_BES);
    const int qr = lane >> 2, qc = lane & 3;
    #pragma unroll
    for (int i = 0; i < 4; i++) {
        #pragma unroll
        for (int j = 0; j < 4; j++) {
            int col = n0w + j * 8 + qc * 2;
            float b0 = bes[col], b1 = bes[col + 1];
            const float* c = acc[i * 4 + j];
            int mA = m0w + i * 16 + qr;
            float v0 = fmaxf(c[0] + b0, 0.f), v1 = fmaxf(c[1] + b1, 0.f);
            float v2 = fmaxf(c[2] + b0, 0.f), v3 = fmaxf(c[3] + b1, 0.f);
            uint32_t p0 = (uint32_t)__half_as_ushort(__float2half_rn(v0))
                        | ((uint32_t)__half_as_ushort(__float2half_rn(v1)) << 16);
            uint32_t p1 = (uint32_t)__half_as_ushort(__float2half_rn(v2))
                        | ((uint32_t)__half_as_ushort(__float2half_rn(v3)) << 16);
            stg[mA * STAGE_PITCH_U32 + (col >> 1)] = p0;
            stg[(mA + 8) * STAGE_PITCH_U32 + (col >> 1)] = p1;
        }
    }
    __syncthreads();
    #pragma unroll
    for (int i = 0; i < 8; i++) {
        int idx = t + 256 * i;
        int row = idx >> 4, q = idx & 15;
        uint4 v = *(const uint4*)((const char*)stg + row * (STAGE_PITCH_U32 * 4) + q * 16);
        *(uint4*)((char*)g_acts + ((size_t)(r0 + row) * H_SZ + h0) * 2 + q * 16) = v;
    }
}

// ---------------------------------------------------------------------------
// Kernel 3: FUSED select+decode (R12 config: 8 CTAs/SM, RS_BATCH=16).
// ---------------------------------------------------------------------------
__device__ __forceinline__ int cnt_ge2(const uint32_t* w, uint32_t mid,
                                       volatile int* cwb, int wid, int lane)
{
    uint32_t mm = mid | (mid << 16);
    uint32_t c2 = 0;
    #pragma unroll
    for (int i = 0; i < 16; i++)
        c2 = __vadd2(c2, __vcmpgeu2(w[i], mm) & 0x00010001u);
    unsigned local = (c2 & 0xFFFFu) + (c2 >> 16);
    unsigned r = __reduce_add_sync(0xffffffffu, local);
    if (lane == 0) cwb[wid] = (int)r;
    __syncthreads();
    int s = 0;
    #pragma unroll
    for (int i = 0; i < 8; i++) s += cwb[i];
    return s;
}

__global__ __launch_bounds__(256, 8) void select_kernel(
    const float* __restrict__ x, const float* __restrict__ W_enc,
    const float* __restrict__ b_enc, const float* __restrict__ b_dec,
    const float* __restrict__ W_dec, float* __restrict__ out,
    int rgBase)
{
    extern __shared__ float sm[];
    float* xs  = sm;                       // [256]
    float* cv  = sm + 256;                 // [CAND_MAX]
    int*   ci  = (int*)(sm + 256 + CAND_MAX);
    float* stg = sm + 256 + 2 * CAND_MAX;  // [RS_BATCH][RS_PITCH]; reused as red buf
    __shared__ int cw8[8][8];
    __shared__ int tot[8];
    __shared__ int cwf[2][8];
    __shared__ int s_cnt;
    __shared__ float rv[K_TOP];
    __shared__ int   ri[K_TOP];

    const int row = rgBase + blockIdx.x;
    const int t = threadIdx.x, wid = t >> 5, lane = t & 31;

    const uint4* arow = (const uint4*)((const char*)g_acts + (size_t)row * H_SZ * 2);
    uint4 q[4];
    #pragma unroll
    for (int i = 0; i < 4; i++) q[i] = arow[t + 256 * i];
    uint32_t* w = (uint32_t*)q;            // 32 u16 values

    const float xv  = x[(size_t)row * D_SZ + t];
    const float bdv = b_dec[t];
    xs[t] = xv - bdv;
    if (t == 0) s_cnt = 0;

    // ---- 8-threshold probe: fp16 grid 2.1 .. 2.8
    const uint32_t TG[8] = {0x4033,0x4066,0x4099,0x40CD,0x4100,0x4133,0x4166,0x419A};
    #pragma unroll
    for (int j = 0; j < 8; j++) {
        uint32_t mm = TG[j] | (TG[j] << 16);
        uint32_t c2 = 0;
        #pragma unroll
        for (int i = 0; i < 16; i++)
            c2 = __vadd2(c2, __vcmpgeu2(w[i], mm) & 0x00010001u);
        unsigned local = (c2 & 0xFFFFu) + (c2 >> 16);
        unsigned r = __reduce_add_sync(0xffffffffu, local);
        if (lane == 0) cw8[wid][j] = (int)r;
    }
    __syncthreads();
    if (t < 8) {
        int s = 0;
        #pragma unroll
        for (int i = 0; i < 8; i++) s += cw8[i][t];
        tot[t] = s;
    }
    __syncthreads();

    int T = -1;
    for (int j = 7; j >= 0; j--) {
        int c = tot[j];
        if (c >= CAND_K) { if (c <= 90) T = (int)TG[j]; break; }
    }
    if (T < 0) {     // rare fallback: full-range exact search for count >= CAND_K
        uint32_t lo = 1, hi = 0x7C00;
        int buf = 0;
        while (hi - lo > 1) {
            uint32_t mid = (lo + hi) >> 1;
            int c = cnt_ge2(w, mid, cwf[buf], wid, lane);
            buf ^= 1;
            if (c >= CAND_K) lo = mid; else hi = mid;
        }
        T = (int)lo;
    }
    const uint32_t Tc = (T > TK_MARGIN) ? (uint32_t)(T - TK_MARGIN) : 1u;

    // ---- collect candidate indices into smem
    #pragma unroll
    for (int i = 0; i < 16; i++) {
        int cbase = (t + 256 * (i >> 2)) * 8 + (i & 3) * 2;
        uint32_t u0 = w[i] & 0xFFFFu, u1 = w[i] >> 16;
        if (u0 >= Tc) {
            int p = atomicAdd(&s_cnt, 1);
            if (p < CAND_MAX) ci[p] = cbase;
        }
        if (u1 >= Tc) {
            int p = atomicAdd(&s_cnt, 1);
            if (p < CAND_MAX) ci[p] = cbase + 1;
        }
    }
    __syncthreads();
    const int cnt = (s_cnt < CAND_MAX) ? s_cnt : CAND_MAX;

    // ---- rescore: staged coalesced, verbatim sequential fmaf chain
    for (int b0 = 0; b0 < cnt; b0 += RS_BATCH) {
        int nb = min(RS_BATCH, cnt - b0);
        for (int j = t; j < nb * 64; j += 256) {
            int r = j >> 6, c4 = j & 63;
            int idx = ci[b0 + r];
            float4 v = __ldg((const float4*)(W_enc + (size_t)idx * D_SZ) + c4);
            *(float4*)(stg + r * RS_PITCH + c4 * 4) = v;
        }
        __syncthreads();
        if (t < nb) {
            int idx = ci[b0 + t];
            const float* wrow = stg + t * RS_PITCH;
            float s = 0.f;
            #pragma unroll 8
            for (int k = 0; k < D_SZ; k++) s = fmaf(xs[k], wrow[k], s);
            cv[b0 + t] = fmaxf(s + b_enc[idx], 0.f);
        }
        __syncthreads();
    }

    // ---- rank -> top-32 (value desc, index asc) + counts
    if (t < K_TOP) { rv[t] = 0.f; ri[t] = 0; }
    __syncthreads();
    if (t < cnt) {
        float v = cv[t]; int id = ci[t];
        int rank = 0;
        for (int j = 0; j < cnt; j++) {
            float vo = cv[j];
            rank += (vo > v) || (vo == v && ci[j] < id);
        }
        if (rank < K_TOP) {
            rv[rank] = v;
            ri[rank] = id;
            atomicAdd(&g_counts[id], 1);
        }
    }
    __syncthreads();

    // ---- decode column t (identical arithmetic/order to the decode kernel)
    float acc = bdv;
    #pragma unroll
    for (int j = 0; j < K_TOP; j++)
        acc += rv[j] * __ldg(&W_dec[(size_t)ri[j] * D_SZ + t]);
    out[(size_t)row * D_SZ + t] = acc;

    float e = acc - xv;
    stg[t] = e * e;
    __syncthreads();
    for (int s = 128; s > 0; s >>= 1) {
        if (t < s) stg[t] += stg[t + s];
        __syncthreads();
    }
    if (t == 0) g_e2part[row] = stg[0];
}

// ---------------------------------------------------------------------------
// Kernel 4: finalize
// ---------------------------------------------------------------------------
__global__ __launch_bounds__(256) void finalize_kernel(float* __restrict__ out)
{
    __shared__ float red[256];
    __shared__ float sh_var, sh_q, sh_e2;
    int t = threadIdx.x;
    float S = 0.f;
    for (int g = 0; g < 64; g++) S += g_colsum[g * D_SZ + t];
    red[t] = S * S * (1.0f / (float)B_SZ);
    __syncthreads();
    for (int s = 128; s > 0; s >>= 1) { if (t < s) red[t] += red[t + s]; __syncthreads(); }
    if (t == 0) sh_var = red[0];
    __syncthreads();
    red[t] = (t < 64) ? g_qpart[t] : 0.f;
    __syncthreads();
    for (int s = 128; s > 0; s >>= 1) { if (t < s) red[t] += red[t + s]; __syncthreads(); }
    if (t == 0) sh_q = red[0];
    __syncthreads();
    float e2 = 0.f;
    for (int i = t; i < B_SZ; i += 256) e2 += g_e2part[i];
    red[t] = e2; __syncthreads();
    for (int s = 128; s > 0; s >>= 1) { if (t < s) red[t] += red[t + s]; __syncthreads(); }
    if (t == 0) sh_e2 = red[0];
    __syncthreads();
    if (t == 0) {
        float total_var = sh_q - sh_var;
        out[(size_t)B_SZ * D_SZ + H_SZ] = sh_e2 / total_var;
    }
    for (int i = t; i < H_SZ; i += 256)
        out[(size_t)B_SZ * D_SZ + i] = (float)g_counts[i];
}

// ---------------------------------------------------------------------------
// Launch: encode on second stream, overlapped with select of prior group.
// 8 groups of 2048 rows -> finer pipelining, smaller exposed first encode.
// ---------------------------------------------------------------------------
static cudaStream_t g_s2 = nullptr;
static cudaEvent_t  g_evC = nullptr;
static cudaEvent_t  g_evE[NGRP];

extern "C" void kernel_launch(void* const* d_in, const int* in_sizes, int n_in,
                              void* d_out, int out_size)
{
    const float* x     = (const float*)d_in[0];
    const float* W_enc = (const float*)d_in[1];
    const float* b_enc = (const float*)d_in[2];
    const float* W_dec = (const float*)d_in[3];
    const float* b_dec = (const float*)d_in[4];
    float* out = (float*)d_out;

    if (g_s2 == nullptr) {
        cudaStreamCreateWithFlags(&g_s2, cudaStreamNonBlocking);
        cudaEventCreateWithFlags(&g_evC, cudaEventDisableTiming);
        for (int g = 0; g < NGRP; g++)
            cudaEventCreateWithFlags(&g_evE[g], cudaEventDisableTiming);
        cudaFuncSetAttribute(encode_kernel,
                             cudaFuncAttributeMaxDynamicSharedMemorySize, ESM2_TOTAL);
        cudaFuncSetAttribute(select_kernel,
                             cudaFuncAttributeMaxDynamicSharedMemorySize, SEL_SMEM_BYTES);
    }

    conv_kernel<<<3072, 256>>>(x, W_enc, b_dec);
    colstat_kernel<<<64, 256>>>(x);
    cudaEventRecord(g_evC, 0);
    cudaStreamWaitEvent(g_s2, g_evC, 0);

    encode_kernel<<<dim3(H_SZ / 128, ROWG / 128), 256, ESM2_TOTAL, g_s2>>>(b_enc, 0);
    cudaEventRecord(g_evE[0], g_s2);

    for (int g = 0; g < NGRP; g++) {
        if (g + 1 < NGRP) {
            encode_kernel<<<dim3(H_SZ / 128, ROWG / 128), 256, ESM2_TOTAL, g_s2>>>(
                b_enc, (g + 1) * ROWG);
            cudaEventRecord(g_evE[g + 1], g_s2);
        }
        cudaStreamWaitEvent(0, g_evE[g], 0);
        select_kernel<<<ROWG, 256, SEL_SMEM_BYTES>>>(
            x, W_enc, b_enc, b_dec, W_dec, out, g * ROWG);
    }
    finalize_kernel<<<1, 256>>>(out);
}

// round 17
// speedup vs baseline: 18.0612x; 1.0829x over previous
#include <cuda_runtime.h>
#include <cuda_fp16.h>
#include <cstdint>

#define B_SZ   16384
#define D_SZ   256
#define H_SZ   8192
#define K_TOP  32
#define CAND_K   36     // min acceptable candidate count at threshold
#define CAND_MAX 96     // candidate buffer cap
#define TK_MARGIN 4     // ulp margin below threshold (covers 2*delta fp16+GEMM err)
#define ROWG   4096     // row-group size (R12 operating point)
#define NGRP   (B_SZ / ROWG)

// select staging — 16-row batches: smem 18.4KB so 8 CTAs/SM fit
#define RS_BATCH 16
#define RS_PITCH 260    // words per staged row (1040B)
#define SEL_SMEM_FLOATS (256 + CAND_MAX + CAND_MAX + RS_BATCH * RS_PITCH)
#define SEL_SMEM_BYTES  (SEL_SMEM_FLOATS * 4)

// ---------------------------------------------------------------------------
// Scratch (__device__ globals)
// ---------------------------------------------------------------------------
__device__ __half g_xh [B_SZ * D_SZ];                 // fp16(x - b_dec)
__device__ __half g_weh[H_SZ * D_SZ];                 // fp16(W_enc)
__device__ __half g_acts[(size_t)B_SZ * H_SZ];        // fp16 relu(pre_acts)
__device__ int   g_counts[H_SZ];
__device__ float g_colsum[64 * D_SZ];
__device__ float g_qpart[64];
__device__ float g_e2part[B_SZ];                      // per-row e^2

// ---------------------------------------------------------------------------
// Helpers
// ---------------------------------------------------------------------------
__device__ __forceinline__ uint32_t smem_u32(const void* p) {
    uint32_t a;
    asm("{ .reg .u64 t; cvta.to.shared.u64 t, %1; cvt.u32.u64 %0, t; }" : "=r"(a) : "l"(p));
    return a;
}
#define CP_ASYNC16(dst, src) \
    asm volatile("cp.async.cg.shared.global [%0], [%1], 16;" :: "r"(dst), "l"(src))
#define CP_COMMIT() asm volatile("cp.async.commit_group;")
#define CP_WAIT(n)  asm volatile("cp.async.wait_group %0;" :: "n"(n))

__device__ __forceinline__ void ldsm_x4(uint32_t& r0, uint32_t& r1, uint32_t& r2, uint32_t& r3,
                                        uint32_t addr) {
    asm volatile("ldmatrix.sync.aligned.m8n8.x4.shared.b16 {%0,%1,%2,%3}, [%4];"
                 : "=r"(r0), "=r"(r1), "=r"(r2), "=r"(r3) : "r"(addr));
}
__device__ __forceinline__ void mma_16816(float* c, uint32_t a0, uint32_t a1, uint32_t a2,
                                          uint32_t a3, uint32_t b0, uint32_t b1) {
    asm volatile(
        "mma.sync.aligned.m16n8k16.row.col.f32.f16.f16.f32 "
        "{%0,%1,%2,%3}, {%4,%5,%6,%7}, {%8,%9}, {%0,%1,%2,%3};"
        : "+f"(c[0]), "+f"(c[1]), "+f"(c[2]), "+f"(c[3])
        : "r"(a0), "r"(a1), "r"(a2), "r"(a3), "r"(b0), "r"(b1));
}

// ---------------------------------------------------------------------------
// Kernel 0: convert x -> fp16(x - b_dec), W_enc -> fp16
// ---------------------------------------------------------------------------
__global__ __launch_bounds__(256) void conv_kernel(
    const float* __restrict__ x, const float* __restrict__ W_enc,
    const float* __restrict__ b_dec)
{
    int b = blockIdx.x, t = threadIdx.x;
    if (b < 2048) {
        size_t e0 = ((size_t)b * 256 + t) * 8;
        int col = (int)(e0 & (D_SZ - 1));
        float4 v0 = *(const float4*)(x + e0);
        float4 v1 = *(const float4*)(x + e0 + 4);
        float4 d0 = *(const float4*)(b_dec + col);
        float4 d1 = *(const float4*)(b_dec + col + 4);
        __half o[8];
        o[0]=__float2half_rn(v0.x-d0.x); o[1]=__float2half_rn(v0.y-d0.y);
        o[2]=__float2half_rn(v0.z-d0.z); o[3]=__float2half_rn(v0.w-d0.w);
        o[4]=__float2half_rn(v1.x-d1.x); o[5]=__float2half_rn(v1.y-d1.y);
        o[6]=__float2half_rn(v1.z-d1.z); o[7]=__float2half_rn(v1.w-d1.w);
        *(uint4*)(g_xh + e0) = *(uint4*)o;
    } else {
        size_t e0 = ((size_t)(b - 2048) * 256 + t) * 8;
        float4 v0 = *(const float4*)(W_enc + e0);
        float4 v1 = *(const float4*)(W_enc + e0 + 4);
        __half o[8];
        o[0]=__float2half_rn(v0.x); o[1]=__float2half_rn(v0.y);
        o[2]=__float2half_rn(v0.z); o[3]=__float2half_rn(v0.w);
        o[4]=__float2half_rn(v1.x); o[5]=__float2half_rn(v1.y);
        o[6]=__float2half_rn(v1.z); o[7]=__float2half_rn(v1.w);
        *(uint4*)(g_weh + e0) = *(uint4*)o;
    }
}

// ---------------------------------------------------------------------------
// Kernel 1: column stats of x + zero counts (runs concurrent with encode(0))
// ---------------------------------------------------------------------------
__global__ __launch_bounds__(256) void colstat_kernel(const float* __restrict__ x)
{
    __shared__ float red[256];
    int g = blockIdx.x, t = threadIdx.x;
    int gid = g * 256 + t;
    if (gid < H_SZ) g_counts[gid] = 0;
    const float* xb = x + (size_t)(g * 256) * D_SZ;
    float s = 0.f, q = 0.f;
    #pragma unroll 8
    for (int r = 0; r < 256; r++) {
        float v = xb[r * D_SZ + t];
        s += v; q += v * v;
    }
    g_colsum[g * D_SZ + t] = s;
    red[t] = q; __syncthreads();
    for (int sft = 128; sft > 0; sft >>= 1) { if (t < sft) red[t] += red[t + sft]; __syncthreads(); }
    if (t == 0) g_qpart[g] = red[0];
}

// ---------------------------------------------------------------------------
// Kernel 2: encoder GEMM via mma.sync (fp16 HMMA), 128x128x256 per block.
// K staged in 4 chunks of 64 (2 buffers); smem 74.2KB -> 2 CTAs/SM.
// ---------------------------------------------------------------------------
#define KC2      64
#define PITCH2   72
#define STG2     (128 * PITCH2 * 2)
#define OFF2_A(p) ((p) * STG2)
#define OFF2_B(p) (2 * STG2 + (p) * STG2)
#define OFF2_BES (4 * STG2)
#define ESM2_TOTAL (OFF2_BES + 512)
#define STAGE_PITCH_U32 68

__global__ __launch_bounds__(256, 2) void encode_kernel(const float* __restrict__ b_enc,
                                                        int rgBase)
{
    extern __shared__ char smem[];
    const uint32_t sbase = smem_u32(smem);
    const int t = threadIdx.x;
    const int wid = t >> 5, lane = t & 31;
    const int h0 = blockIdx.x * 128;
    const int r0 = rgBase + blockIdx.y * 128;

    const int wm = wid >> 2, wn = wid & 3;
    const int m0w = wm * 64, n0w = wn * 32;

    const char* gA = (const char*)(g_xh  + (size_t)r0 * D_SZ);
    const char* gB = (const char*)(g_weh + (size_t)h0 * D_SZ);

    auto load_stage = [&](int s, int p) {
        #pragma unroll
        for (int i = 0; i < 4; i++) {
            int idx = t + 256 * i;
            int row = idx >> 3, q = idx & 7;
            uint32_t dOff = (uint32_t)((row * PITCH2 + q * 8) * 2);
            size_t gOff = ((size_t)row * D_SZ + s * KC2 + q * 8) * 2;
            CP_ASYNC16(sbase + OFF2_A(p) + dOff, gA + gOff);
            CP_ASYNC16(sbase + OFF2_B(p) + dOff, gB + gOff);
        }
        CP_COMMIT();
    };

    load_stage(0, 0);
    load_stage(1, 1);
    ((float*)(smem + OFF2_BES))[t & 127] = b_enc[h0 + (t & 127)];

    float acc[16][4];
    #pragma unroll
    for (int f = 0; f < 16; f++)
        #pragma unroll
        for (int e = 0; e < 4; e++) acc[f][e] = 0.f;

    const int aRow = lane & 15;
    const int aCol = (lane >> 4) << 3;
    const int bRow = ((lane >> 4) << 3) + (lane & 7);
    const int bCol = ((lane >> 3) & 1) << 3;

    CP_WAIT(1);
    __syncthreads();

    #pragma unroll
    for (int s = 0; s < 4; s++) {
        const int p = s & 1;
        const uint32_t aBase = sbase + OFF2_A(p) + ((m0w + aRow) * PITCH2 + aCol) * 2;
        const uint32_t bBase = sbase + OFF2_B(p) + ((n0w + bRow) * PITCH2 + bCol) * 2;
        #pragma unroll
        for (int k0 = 0; k0 < KC2; k0 += 16) {
            uint32_t a[4][4], b[2][4];
            #pragma unroll
            for (int i = 0; i < 4; i++)
                ldsm_x4(a[i][0], a[i][1], a[i][2], a[i][3],
                        aBase + (i * 16 * PITCH2 + k0) * 2);
            #pragma unroll
            for (int jp = 0; jp < 2; jp++)
                ldsm_x4(b[jp][0], b[jp][1], b[jp][2], b[jp][3],
                        bBase + (jp * 16 * PITCH2 + k0) * 2);
            #pragma unroll
            for (int i = 0; i < 4; i++)
                #pragma unroll
                for (int j = 0; j < 4; j++)
                    mma_16816(acc[i * 4 + j], a[i][0], a[i][1], a[i][2], a[i][3],
                              b[j >> 1][(j & 1) * 2], b[j >> 1][(j & 1) * 2 + 1]);
        }
        if (s < 2) {
            __syncthreads();
            load_stage(s + 2, p);
            CP_WAIT(1);
            __syncthreads();
        } else if (s == 2) {
            CP_WAIT(0);
            __syncthreads();
        }
    }
    __syncthreads();

    uint32_t* stg = (uint32_t*)smem;
    const float* bes = (const float*)(smem + OFF2_BES);
    const int qr = lane >> 2, qc = lane & 3;
    #pragma unroll
    for (int i = 0; i < 4; i++) {
        #pragma unroll
        for (int j = 0; j < 4; j++) {
            int col = n0w + j * 8 + qc * 2;
            float b0 = bes[col], b1 = bes[col + 1];
            const float* c = acc[i * 4 + j];
            int mA = m0w + i * 16 + qr;
            float v0 = fmaxf(c[0] + b0, 0.f), v1 = fmaxf(c[1] + b1, 0.f);
            float v2 = fmaxf(c[2] + b0, 0.f), v3 = fmaxf(c[3] + b1, 0.f);
            uint32_t p0 = (uint32_t)__half_as_ushort(__float2half_rn(v0))
                        | ((uint32_t)__half_as_ushort(__float2half_rn(v1)) << 16);
            uint32_t p1 = (uint32_t)__half_as_ushort(__float2half_rn(v2))
                        | ((uint32_t)__half_as_ushort(__float2half_rn(v3)) << 16);
            stg[mA * STAGE_PITCH_U32 + (col >> 1)] = p0;
            stg[(mA + 8) * STAGE_PITCH_U32 + (col >> 1)] = p1;
        }
    }
    __syncthreads();
    #pragma unroll
    for (int i = 0; i < 8; i++) {
        int idx = t + 256 * i;
        int row = idx >> 4, q = idx & 15;
        uint4 v = *(const uint4*)((const char*)stg + row * (STAGE_PITCH_U32 * 4) + q * 16);
        *(uint4*)((char*)g_acts + ((size_t)(r0 + row) * H_SZ + h0) * 2 + q * 16) = v;
    }
}

// ---------------------------------------------------------------------------
// Kernel 3: FUSED select+decode (R12 logic; e^2 reduce via warp shuffles)
// ---------------------------------------------------------------------------
__device__ __forceinline__ int cnt_ge2(const uint32_t* w, uint32_t mid,
                                       volatile int* cwb, int wid, int lane)
{
    uint32_t mm = mid | (mid << 16);
    uint32_t c2 = 0;
    #pragma unroll
    for (int i = 0; i < 16; i++)
        c2 = __vadd2(c2, __vcmpgeu2(w[i], mm) & 0x00010001u);
    unsigned local = (c2 & 0xFFFFu) + (c2 >> 16);
    unsigned r = __reduce_add_sync(0xffffffffu, local);
    if (lane == 0) cwb[wid] = (int)r;
    __syncthreads();
    int s = 0;
    #pragma unroll
    for (int i = 0; i < 8; i++) s += cwb[i];
    return s;
}

__global__ __launch_bounds__(256, 8) void select_kernel(
    const float* __restrict__ x, const float* __restrict__ W_enc,
    const float* __restrict__ b_enc, const float* __restrict__ b_dec,
    const float* __restrict__ W_dec, float* __restrict__ out,
    int rgBase)
{
    extern __shared__ float sm[];
    float* xs  = sm;                       // [256]
    float* cv  = sm + 256;                 // [CAND_MAX]
    int*   ci  = (int*)(sm + 256 + CAND_MAX);
    float* stg = sm + 256 + 2 * CAND_MAX;  // [RS_BATCH][RS_PITCH]
    __shared__ int cw8[8][8];
    __shared__ int tot[8];
    __shared__ int cwf[2][8];
    __shared__ int s_cnt;
    __shared__ float rv[K_TOP];
    __shared__ int   ri[K_TOP];
    __shared__ float e2w[8];

    const int row = rgBase + blockIdx.x;
    const int t = threadIdx.x, wid = t >> 5, lane = t & 31;

    const uint4* arow = (const uint4*)((const char*)g_acts + (size_t)row * H_SZ * 2);
    uint4 q[4];
    #pragma unroll
    for (int i = 0; i < 4; i++) q[i] = arow[t + 256 * i];
    uint32_t* w = (uint32_t*)q;            // 32 u16 values

    const float xv  = x[(size_t)row * D_SZ + t];
    const float bdv = b_dec[t];
    xs[t] = xv - bdv;
    if (t == 0) s_cnt = 0;

    // ---- 8-threshold probe: fp16 grid 2.1 .. 2.8
    const uint32_t TG[8] = {0x4033,0x4066,0x4099,0x40CD,0x4100,0x4133,0x4166,0x419A};
    #pragma unroll
    for (int j = 0; j < 8; j++) {
        uint32_t mm = TG[j] | (TG[j] << 16);
        uint32_t c2 = 0;
        #pragma unroll
        for (int i = 0; i < 16; i++)
            c2 = __vadd2(c2, __vcmpgeu2(w[i], mm) & 0x00010001u);
        unsigned local = (c2 & 0xFFFFu) + (c2 >> 16);
        unsigned r = __reduce_add_sync(0xffffffffu, local);
        if (lane == 0) cw8[wid][j] = (int)r;
    }
    __syncthreads();
    if (t < 8) {
        int s = 0;
        #pragma unroll
        for (int i = 0; i < 8; i++) s += cw8[i][t];
        tot[t] = s;
    }
    __syncthreads();

    int T = -1;
    for (int j = 7; j >= 0; j--) {
        int c = tot[j];
        if (c >= CAND_K) { if (c <= 90) T = (int)TG[j]; break; }
    }
    if (T < 0) {     // rare fallback: full-range exact search for count >= CAND_K
        uint32_t lo = 1, hi = 0x7C00;
        int buf = 0;
        while (hi - lo > 1) {
            uint32_t mid = (lo + hi) >> 1;
            int c = cnt_ge2(w, mid, cwf[buf], wid, lane);
            buf ^= 1;
            if (c >= CAND_K) lo = mid; else hi = mid;
        }
        T = (int)lo;
    }
    const uint32_t Tc = (T > TK_MARGIN) ? (uint32_t)(T - TK_MARGIN) : 1u;

    // ---- collect candidate indices into smem
    #pragma unroll
    for (int i = 0; i < 16; i++) {
        int cbase = (t + 256 * (i >> 2)) * 8 + (i & 3) * 2;
        uint32_t u0 = w[i] & 0xFFFFu, u1 = w[i] >> 16;
        if (u0 >= Tc) {
            int p = atomicAdd(&s_cnt, 1);
            if (p < CAND_MAX) ci[p] = cbase;
        }
        if (u1 >= Tc) {
            int p = atomicAdd(&s_cnt, 1);
            if (p < CAND_MAX) ci[p] = cbase + 1;
        }
    }
    __syncthreads();
    const int cnt = (s_cnt < CAND_MAX) ? s_cnt : CAND_MAX;

    // ---- rescore: staged coalesced, verbatim sequential fmaf chain
    for (int b0 = 0; b0 < cnt; b0 += RS_BATCH) {
        int nb = min(RS_BATCH, cnt - b0);
        for (int j = t; j < nb * 64; j += 256) {
            int r = j >> 6, c4 = j & 63;
            int idx = ci[b0 + r];
            float4 v = __ldg((const float4*)(W_enc + (size_t)idx * D_SZ) + c4);
            *(float4*)(stg + r * RS_PITCH + c4 * 4) = v;
        }
        __syncthreads();
        if (t < nb) {
            int idx = ci[b0 + t];
            const float* wrow = stg + t * RS_PITCH;
            float s = 0.f;
            #pragma unroll 8
            for (int k = 0; k < D_SZ; k++) s = fmaf(xs[k], wrow[k], s);
            cv[b0 + t] = fmaxf(s + b_enc[idx], 0.f);
        }
        __syncthreads();
    }

    // ---- rank -> top-32 (value desc, index asc) + counts
    if (t < K_TOP) { rv[t] = 0.f; ri[t] = 0; }
    __syncthreads();
    if (t < cnt) {
        float v = cv[t]; int id = ci[t];
        int rank = 0;
        for (int j = 0; j < cnt; j++) {
            float vo = cv[j];
            rank += (vo > v) || (vo == v && ci[j] < id);
        }
        if (rank < K_TOP) {
            rv[rank] = v;
            ri[rank] = id;
            atomicAdd(&g_counts[id], 1);
        }
    }
    __syncthreads();

    // ---- decode column t (identical arithmetic/order to the decode kernel)
    float acc = bdv;
    #pragma unroll
    for (int j = 0; j < K_TOP; j++)
        acc += rv[j] * __ldg(&W_dec[(size_t)ri[j] * D_SZ + t]);
    out[(size_t)row * D_SZ + t] = acc;

    // ---- e^2: warp shuffle reduce + single barrier (order change only
    //      affects the fvu scalar at ~1e-7; tolerance is 1e-3)
    float e = acc - xv;
    float es = e * e;
    #pragma unroll
    for (int off = 16; off > 0; off >>= 1)
        es += __shfl_down_sync(0xffffffffu, es, off);
    if (lane == 0) e2w[wid] = es;
    __syncthreads();
    if (t == 0) {
        float s = 0.f;
        #pragma unroll
        for (int i = 0; i < 8; i++) s += e2w[i];
        g_e2part[row] = s;
    }
}

// ---------------------------------------------------------------------------
// Kernel 4: finalize
// ---------------------------------------------------------------------------
__global__ __launch_bounds__(256) void finalize_kernel(float* __restrict__ out)
{
    __shared__ float red[256];
    __shared__ float sh_var, sh_q, sh_e2;
    int t = threadIdx.x;
    float S = 0.f;
    for (int g = 0; g < 64; g++) S += g_colsum[g * D_SZ + t];
    red[t] = S * S * (1.0f / (float)B_SZ);
    __syncthreads();
    for (int s = 128; s > 0; s >>= 1) { if (t < s) red[t] += red[t + s]; __syncthreads(); }
    if (t == 0) sh_var = red[0];
    __syncthreads();
    red[t] = (t < 64) ? g_qpart[t] : 0.f;
    __syncthreads();
    for (int s = 128; s > 0; s >>= 1) { if (t < s) red[t] += red[t + s]; __syncthreads(); }
    if (t == 0) sh_q = red[0];
    __syncthreads();
    float e2 = 0.f;
    for (int i = t; i < B_SZ; i += 256) e2 += g_e2part[i];
    red[t] = e2; __syncthreads();
    for (int s = 128; s > 0; s >>= 1) { if (t < s) red[t] += red[t + s]; __syncthreads(); }
    if (t == 0) sh_e2 = red[0];
    __syncthreads();
    if (t == 0) {
        float total_var = sh_q - sh_var;
        out[(size_t)B_SZ * D_SZ + H_SZ] = sh_e2 / total_var;
    }
    for (int i = t; i < H_SZ; i += 256)
        out[(size_t)B_SZ * D_SZ + i] = (float)g_counts[i];
}

// ---------------------------------------------------------------------------
// Launch: conv -> event -> encode chain on s2 starts immediately;
// colstat runs on stream 0 CONCURRENT with encode(0) (it only feeds
// select(0)/finalize). select(g) waits evE[g].
// ---------------------------------------------------------------------------
static cudaStream_t g_s2 = nullptr;
static cudaEvent_t  g_evC = nullptr;
static cudaEvent_t  g_evE[NGRP];

extern "C" void kernel_launch(void* const* d_in, const int* in_sizes, int n_in,
                              void* d_out, int out_size)
{
    const float* x     = (const float*)d_in[0];
    const float* W_enc = (const float*)d_in[1];
    const float* b_enc = (const float*)d_in[2];
    const float* W_dec = (const float*)d_in[3];
    const float* b_dec = (const float*)d_in[4];
    float* out = (float*)d_out;

    if (g_s2 == nullptr) {
        cudaStreamCreateWithFlags(&g_s2, cudaStreamNonBlocking);
        cudaEventCreateWithFlags(&g_evC, cudaEventDisableTiming);
        for (int g = 0; g < NGRP; g++)
            cudaEventCreateWithFlags(&g_evE[g], cudaEventDisableTiming);
        cudaFuncSetAttribute(encode_kernel,
                             cudaFuncAttributeMaxDynamicSharedMemorySize, ESM2_TOTAL);
        cudaFuncSetAttribute(select_kernel,
                             cudaFuncAttributeMaxDynamicSharedMemorySize, SEL_SMEM_BYTES);
    }

    conv_kernel<<<3072, 256>>>(x, W_enc, b_dec);
    cudaEventRecord(g_evC, 0);
    cudaStreamWaitEvent(g_s2, g_evC, 0);

    encode_kernel<<<dim3(H_SZ / 128, ROWG / 128), 256, ESM2_TOTAL, g_s2>>>(b_enc, 0);
    cudaEventRecord(g_evE[0], g_s2);

    colstat_kernel<<<64, 256>>>(x);   // overlaps encode(0); precedes select(0)

    for (int g = 0; g < NGRP; g++) {
        if (g + 1 < NGRP) {
            encode_kernel<<<dim3(H_SZ / 128, ROWG / 128), 256, ESM2_TOTAL, g_s2>>>(
                b_enc, (g + 1) * ROWG);
            cudaEventRecord(g_evE[g + 1], g_s2);
        }
        cudaStreamWaitEvent(0, g_evE[g], 0);
        select_kernel<<<ROWG, 256, SEL_SMEM_BYTES>>>(
            x, W_enc, b_enc, b_dec, W_dec, out, g * ROWG);
    }
    finalize_kernel<<<1, 256>>>(out);
}